// round 11
// baseline (speedup 1.0000x reference)
#include <cuda_runtime.h>
#include <cuda_fp16.h>
#include <math.h>
#include <stdint.h>

#define B_    2
#define S_    1024
#define D_    2048
#define H_    32
#define HKV_  8
#define HD_   64
#define REP_  4
#define M_    (B_ * S_)       // 2048
#define NQ_   (H_ * HD_)      // 2048
#define NKV_  (HKV_ * HD_)    // 512

// ---------------------------------------------------------------------------
// Device-global scratch (no cudaMalloc allowed)
// ---------------------------------------------------------------------------
__device__ __half g_xh [M_ * D_];
__device__ __half g_wqt[NQ_ * D_];     // wq^T  [N][K]
__device__ __half g_wkt[NKV_ * D_];
__device__ __half g_wvt[NKV_ * D_];
__device__ __half g_wot[D_ * NQ_];     // wo^T
__device__ __half g_qh [M_ * NQ_];     // q (rope applied)
__device__ __half g_kh [M_ * NKV_];    // k (rope applied)
__device__ __half g_vt [B_ * HKV_ * HD_ * S_];  // v transposed: [b][gh][d][s]
__device__ __half g_ctxh[M_ * NQ_];

// ---------------------------------------------------------------------------
// Persistent streams/events: created once at module load (pre-main, before
// the harness memory baseline). kernel_launch never creates/destroys.
// ---------------------------------------------------------------------------
struct StreamCtx {
    cudaStream_t s1, s2, s3;
    cudaEvent_t eFork, eConv1, eTqkv, eWo;
    cudaEvent_t eQ00, eQ01, eQ10, eQ11;
    cudaEvent_t eF00, eF01, eF10, eF11;
    cudaEvent_t eB1;
    StreamCtx() {
        cudaStreamCreateWithFlags(&s1, cudaStreamNonBlocking);
        cudaStreamCreateWithFlags(&s2, cudaStreamNonBlocking);
        cudaStreamCreateWithFlags(&s3, cudaStreamNonBlocking);
        cudaEvent_t* evs[] = {&eFork, &eConv1, &eTqkv, &eWo,
                              &eQ00, &eQ01, &eQ10, &eQ11,
                              &eF00, &eF01, &eF10, &eF11, &eB1};
        for (auto e : evs) cudaEventCreateWithFlags(e, cudaEventDisableTiming);
    }
};
static StreamCtx g_sc;

// ---------------------------------------------------------------------------
// device helpers
// ---------------------------------------------------------------------------
__device__ __forceinline__ void mma_f16(float* c,
        uint32_t a0, uint32_t a1, uint32_t a2, uint32_t a3,
        uint32_t b0, uint32_t b1) {
    asm volatile(
        "mma.sync.aligned.m16n8k16.row.col.f32.f16.f16.f32 "
        "{%0,%1,%2,%3}, {%4,%5,%6,%7}, {%8,%9}, {%0,%1,%2,%3};"
        : "+f"(c[0]), "+f"(c[1]), "+f"(c[2]), "+f"(c[3])
        : "r"(a0), "r"(a1), "r"(a2), "r"(a3), "r"(b0), "r"(b1));
}

__device__ __forceinline__ void ldsm_x4(uint32_t& r0, uint32_t& r1,
                                        uint32_t& r2, uint32_t& r3, uint32_t addr) {
    asm volatile("ldmatrix.sync.aligned.m8n8.x4.shared.b16 {%0,%1,%2,%3}, [%4];"
                 : "=r"(r0), "=r"(r1), "=r"(r2), "=r"(r3) : "r"(addr));
}

__device__ __forceinline__ void cp16(uint32_t saddr, const void* gptr) {
    asm volatile("cp.async.cg.shared.global [%0], [%1], 16;"
                 :: "r"(saddr), "l"(gptr) : "memory");
}
__device__ __forceinline__ void cp_commit() {
    asm volatile("cp.async.commit_group;" ::: "memory");
}
__device__ __forceinline__ void cp_wait2() {
    asm volatile("cp.async.wait_group 2;" ::: "memory");
}
__device__ __forceinline__ void cp_wait1() {
    asm volatile("cp.async.wait_group 1;" ::: "memory");
}
__device__ __forceinline__ void cp_wait0() {
    asm volatile("cp.async.wait_group 0;" ::: "memory");
}

// ---------------------------------------------------------------------------
// Converters
// ---------------------------------------------------------------------------
__global__ void conv_x(const float* __restrict__ x, __half* __restrict__ xh, int n4)
{
    int i = blockIdx.x * 256 + threadIdx.x;
    if (i >= n4) return;
    float4 v = ((const float4*)x)[i];
    ((__half2*)xh)[i * 2]     = __floats2half2_rn(v.x, v.y);
    ((__half2*)xh)[i * 2 + 1] = __floats2half2_rn(v.z, v.w);
}

__global__ void transp(const float* __restrict__ s0, const float* __restrict__ s1,
                       __half* __restrict__ d0, __half* __restrict__ d1, int N)
{
    const float* src = blockIdx.z ? s1 : s0;
    __half*      dst = blockIdx.z ? d1 : d0;
    __shared__ float t[32][33];
    int n0 = blockIdx.x * 32, k0 = blockIdx.y * 32;
    int x = threadIdx.x, y = threadIdx.y;
#pragma unroll
    for (int j = 0; j < 32; j += 8)
        t[y + j][x] = src[(size_t)(k0 + y + j) * N + n0 + x];
    __syncthreads();
#pragma unroll
    for (int j = 0; j < 32; j += 8)
        dst[(size_t)(n0 + y + j) * D_ + k0 + x] = __float2half(t[x][y + j]);
}

// ---------------------------------------------------------------------------
// QKV GEMM: 128x64 CTA tiles, 4 warps (warp tile 32x64), cp.async 4-stage.
// Per-chunk: grid (48, 4) covers 512 rows starting at mbase.
// ---------------------------------------------------------------------------
#define GP     40
#define A2_B   (128 * GP * 2)
#define ST2_B  (192 * GP * 2)
#define NSTG   4
#define NITER  (D_ / 32)

__global__ __launch_bounds__(128, 3) void gemm_qkv(
    const __half* __restrict__ A,
    const __half* __restrict__ W0, const __half* __restrict__ W1,
    const __half* __restrict__ W2,
    const float* __restrict__ cosb, const float* __restrict__ sinb,
    int mbase)
{
    extern __shared__ __half sh[];
    const int bx = blockIdx.x, by = blockIdx.y;
    const int tid = threadIdx.x, lane = tid & 31, wid = tid >> 5;
    const int g = lane >> 2, t = lane & 3;
    const int wm = wid * 32;

    const __half* Wt;
    int ctile, sel;
    if (bx < 32)      { Wt = W0; ctile = bx;      sel = 0; }
    else if (bx < 40) { Wt = W1; ctile = bx - 32; sel = 1; }
    else              { Wt = W2; ctile = bx - 40; sel = 2; }

    const __half* Ab = A  + (size_t)(mbase + by * 128) * D_;
    const __half* Bb = Wt + (size_t)ctile * 64 * D_;

    const uint32_t sbase = (uint32_t)__cvta_generic_to_shared(sh);

    auto issue = [&](int stage, int k0) {
        uint32_t sa = sbase + stage * ST2_B;
#pragma unroll
        for (int j = 0; j < 4; j++) {
            int idx = tid + j * 128;
            int r = idx >> 2, c = idx & 3;
            cp16(sa + (r * GP + c * 8) * 2, Ab + (size_t)r * D_ + k0 + c * 8);
        }
#pragma unroll
        for (int j = 0; j < 2; j++) {
            int idx = tid + j * 128;
            int r = idx >> 2, c = idx & 3;
            cp16(sa + A2_B + (r * GP + c * 8) * 2, Bb + (size_t)r * D_ + k0 + c * 8);
        }
    };

    uint32_t aoff[2], boff[4];
#pragma unroll
    for (int mt = 0; mt < 2; mt++)
        aoff[mt] = ((wm + mt * 16 + (lane & 7) + ((lane >> 3) & 1) * 8) * GP
                    + (lane >> 4) * 8) * 2;
#pragma unroll
    for (int p = 0; p < 4; p++)
        boff[p] = (uint32_t)A2_B +
                  ((p * 16 + (lane & 7) + ((lane >> 4) & 1) * 8) * GP
                   + ((lane >> 3) & 1) * 8) * 2;

    float acc[2][8][4] = {};

    issue(0, 0);  cp_commit();
    issue(1, 32); cp_commit();
    issue(2, 64); cp_commit();

    for (int it = 0; it < NITER; ++it) {
        cp_wait2();
        __syncthreads();
        if (it + 3 < NITER) issue((it + 3) & 3, (it + 3) * 32);
        cp_commit();

        const uint32_t sstg = sbase + (uint32_t)(it & 3) * ST2_B;
#pragma unroll
        for (int kk = 0; kk < 2; kk++) {
            const uint32_t kb = kk * 32;
            uint32_t af[2][4];
#pragma unroll
            for (int mt = 0; mt < 2; mt++)
                ldsm_x4(af[mt][0], af[mt][1], af[mt][2], af[mt][3],
                        sstg + aoff[mt] + kb);
            uint32_t bf[8][2];
#pragma unroll
            for (int p = 0; p < 4; p++)
                ldsm_x4(bf[2 * p][0], bf[2 * p][1], bf[2 * p + 1][0], bf[2 * p + 1][1],
                        sstg + boff[p] + kb);
#pragma unroll
            for (int mt = 0; mt < 2; mt++)
#pragma unroll
                for (int nt = 0; nt < 8; nt++)
                    mma_f16(acc[mt][nt], af[mt][0], af[mt][1], af[mt][2], af[mt][3],
                            bf[nt][0], bf[nt][1]);
        }
    }

#pragma unroll
    for (int mt = 0; mt < 2; mt++) {
        const int r0g = mbase + by * 128 + wm + mt * 16 + g;
        const int r1g = r0g + 8;

        if (sel == 2) {
            int b0 = r0g >> 10, s0 = r0g & (S_ - 1);
            int b1 = r1g >> 10, s1 = r1g & (S_ - 1);
#pragma unroll
            for (int nt = 0; nt < 8; nt++) {
                int colk = ctile * 64 + nt * 8 + t * 2;
                int gh = colk >> 6, d = colk & 63;
                size_t base0 = ((size_t)(b0 * HKV_ + gh) * HD_) * S_;
                size_t base1 = ((size_t)(b1 * HKV_ + gh) * HD_) * S_;
                g_vt[base0 + (size_t)d * S_ + s0]       = __float2half(acc[mt][nt][0]);
                g_vt[base0 + (size_t)(d + 1) * S_ + s0] = __float2half(acc[mt][nt][1]);
                g_vt[base1 + (size_t)d * S_ + s1]       = __float2half(acc[mt][nt][2]);
                g_vt[base1 + (size_t)(d + 1) * S_ + s1] = __float2half(acc[mt][nt][3]);
            }
        } else {
            int s0 = r0g & (S_ - 1), s1 = r1g & (S_ - 1);
#pragma unroll
            for (int nt = 0; nt < 4; nt++) {
                int d = nt * 8 + 2 * t;
                float c0a = cosb[s0 * HD_ + d], c0b = cosb[s0 * HD_ + d + 1];
                float z0a = sinb[s0 * HD_ + d], z0b = sinb[s0 * HD_ + d + 1];
                float c1a = cosb[s1 * HD_ + d], c1b = cosb[s1 * HD_ + d + 1];
                float z1a = sinb[s1 * HD_ + d], z1b = sinb[s1 * HD_ + d + 1];
                float a, b;
                a = acc[mt][nt][0]; b = acc[mt][nt + 4][0];
                acc[mt][nt][0] = a * c0a - b * z0a;  acc[mt][nt + 4][0] = b * c0a + a * z0a;
                a = acc[mt][nt][1]; b = acc[mt][nt + 4][1];
                acc[mt][nt][1] = a * c0b - b * z0b;  acc[mt][nt + 4][1] = b * c0b + a * z0b;
                a = acc[mt][nt][2]; b = acc[mt][nt + 4][2];
                acc[mt][nt][2] = a * c1a - b * z1a;  acc[mt][nt + 4][2] = b * c1a + a * z1a;
                a = acc[mt][nt][3]; b = acc[mt][nt + 4][3];
                acc[mt][nt][3] = a * c1b - b * z1b;  acc[mt][nt + 4][3] = b * c1b + a * z1b;
            }
            __half* dst = (sel == 0) ? g_qh : g_kh;
            const int pitch = (sel == 0) ? NQ_ : NKV_;
            const int cb = ctile * 64;
#pragma unroll
            for (int nt = 0; nt < 8; nt++) {
                int col = cb + nt * 8 + t * 2;
                *(__half2*)&dst[(size_t)r0g * pitch + col] =
                    __floats2half2_rn(acc[mt][nt][0], acc[mt][nt][1]);
                *(__half2*)&dst[(size_t)r1g * pitch + col] =
                    __floats2half2_rn(acc[mt][nt][2], acc[mt][nt][3]);
            }
        }
    }
}

// ---------------------------------------------------------------------------
// O-projection GEMM: 128x128 CTA tiles, per-chunk grid (16, 4).
// ---------------------------------------------------------------------------
#define ST_B  (2 * 128 * GP * 2)
#define AB_B  (128 * GP * 2)

__global__ __launch_bounds__(128, 2) void gemm_o(
    const __half* __restrict__ A,
    const __half* __restrict__ W0,
    float* __restrict__ Cf, int mbase)
{
    extern __shared__ __half sh[];
    const int bx = blockIdx.x, by = blockIdx.y;
    const int tid = threadIdx.x, lane = tid & 31, wid = tid >> 5;
    const int g = lane >> 2, t = lane & 3;
    const int wm = (wid & 1) * 64, wn = (wid >> 1) * 64;

    const __half* Ab = A  + (size_t)(mbase + by * 128) * D_;
    const __half* Bb = W0 + (size_t)bx * 128 * D_;

    const uint32_t sbase = (uint32_t)__cvta_generic_to_shared(sh);

    auto issue = [&](int stage, int k0) {
        uint32_t sa = sbase + stage * ST_B;
#pragma unroll
        for (int j = 0; j < 4; j++) {
            int idx = tid + j * 128;
            int r = idx >> 2, c = idx & 3;
            cp16(sa +        (r * GP + c * 8) * 2, Ab + (size_t)r * D_ + k0 + c * 8);
            cp16(sa + AB_B + (r * GP + c * 8) * 2, Bb + (size_t)r * D_ + k0 + c * 8);
        }
    };

    uint32_t aoff[4], boff[4];
#pragma unroll
    for (int mt = 0; mt < 4; mt++)
        aoff[mt] = ((wm + mt * 16 + (lane & 7) + ((lane >> 3) & 1) * 8) * GP
                    + (lane >> 4) * 8) * 2;
#pragma unroll
    for (int p = 0; p < 4; p++)
        boff[p] = (uint32_t)AB_B +
                  ((wn + p * 16 + (lane & 7) + ((lane >> 4) & 1) * 8) * GP
                   + ((lane >> 3) & 1) * 8) * 2;

    float acc[4][8][4] = {};

    issue(0, 0);  cp_commit();
    issue(1, 32); cp_commit();
    issue(2, 64); cp_commit();

    for (int it = 0; it < NITER; ++it) {
        cp_wait2();
        __syncthreads();
        if (it + 3 < NITER) issue((it + 3) & 3, (it + 3) * 32);
        cp_commit();

        const uint32_t sstg = sbase + (uint32_t)(it & 3) * ST_B;
#pragma unroll
        for (int kk = 0; kk < 2; kk++) {
            const uint32_t kb = kk * 32;
            uint32_t af[4][4];
#pragma unroll
            for (int mt = 0; mt < 4; mt++)
                ldsm_x4(af[mt][0], af[mt][1], af[mt][2], af[mt][3],
                        sstg + aoff[mt] + kb);
            uint32_t bf[8][2];
#pragma unroll
            for (int p = 0; p < 4; p++)
                ldsm_x4(bf[2 * p][0], bf[2 * p][1], bf[2 * p + 1][0], bf[2 * p + 1][1],
                        sstg + boff[p] + kb);
#pragma unroll
            for (int mt = 0; mt < 4; mt++)
#pragma unroll
                for (int nt = 0; nt < 8; nt++)
                    mma_f16(acc[mt][nt], af[mt][0], af[mt][1], af[mt][2], af[mt][3],
                            bf[nt][0], bf[nt][1]);
        }
    }

#pragma unroll
    for (int mt = 0; mt < 4; mt++) {
        const int r0g = mbase + by * 128 + wm + mt * 16 + g;
        const int r1g = r0g + 8;
#pragma unroll
        for (int nt = 0; nt < 8; nt++) {
            int col = bx * 128 + wn + nt * 8 + t * 2;
            *(float2*)&Cf[(size_t)r0g * NQ_ + col] =
                make_float2(acc[mt][nt][0], acc[mt][nt][1]);
            *(float2*)&Cf[(size_t)r1g * NQ_ + col] =
                make_float2(acc[mt][nt][2], acc[mt][nt][3]);
        }
    }
}

// ---------------------------------------------------------------------------
// Flash attention: per-chunk, grid (4, 32), q tiles [qt0, qt0+4).
// ---------------------------------------------------------------------------
#define FP_   72
#define FPW_  36
#define KVT_B (64 * FP_ * 2)
#define FQ_OFF 0
#define FK_OFF 18432
#define FV_OFF 36864
#define FPOFF  55296
#define FSMEM  73728

__global__ __launch_bounds__(256) void flash_h(
    const __half* __restrict__ Q,
    const __half* __restrict__ K,
    const __half* __restrict__ Vt,
    __half* __restrict__ Ctx, int b, int qt0)
{
    extern __shared__ __half fsh[];
    const uint32_t sb  = (uint32_t)__cvta_generic_to_shared(fsh);
    const uint32_t qsb = sb + FQ_OFF;
    const uint32_t ksb = sb + FK_OFF;
    const uint32_t vsb = sb + FV_OFF;
    const uint32_t psb = sb + FPOFF;
    __half* Ps = fsh + FPOFF / 2;

    const int qt  = blockIdx.x + qt0;
    const int h   = blockIdx.y;
    const int gh  = h / REP_;
    const int tid = threadIdx.x;
    const int lane = tid & 31;
    const int wid  = tid >> 5;
    const int g    = lane >> 2;
    const int t    = lane & 3;
    const int r0   = wid * 16 + g;
    const int ktmax = 2 * qt + 1;

    const uint32_t aoff = ((wid * 16 + (lane & 7) + ((lane >> 3) & 1) * 8) * FP_
                           + (lane >> 4) * 8) * 2;
    uint32_t boff[4];
#pragma unroll
    for (int p = 0; p < 4; p++)
        boff[p] = ((p * 16 + (lane & 7) + ((lane >> 4) & 1) * 8) * FP_
                   + ((lane >> 3) & 1) * 8) * 2;

    const __half* Qb = Q + ((size_t)(b * S_ + qt * 128)) * NQ_ + h * HD_;
#pragma unroll
    for (int j = 0; j < 4; j++) {
        int idx = tid + j * 256;
        int r = idx >> 3, c = (idx & 7) * 8;
        *(uint4*)&fsh[(FQ_OFF / 2) + r * FP_ + c] =
            *(const uint4*)(Qb + (size_t)r * NQ_ + c);
    }

    const __half* Kbase  = K  + ((size_t)(b * S_)) * NKV_ + gh * HD_;
    const __half* Vtbase = Vt + ((size_t)(b * HKV_ + gh)) * HD_ * S_;
    auto loadKV = [&](int st, int kt) {
        uint32_t kst = ksb + st * KVT_B;
        uint32_t vst = vsb + st * KVT_B;
        const __half* Kb  = Kbase  + (size_t)(kt * 64) * NKV_;
        const __half* Vtb = Vtbase + kt * 64;
#pragma unroll
        for (int j = 0; j < 2; j++) {
            int idx = tid + j * 256;
            int r = idx >> 3, c = idx & 7;
            cp16(kst + r * 144 + c * 16, Kb  + (size_t)r * NKV_ + c * 8);
            cp16(vst + r * 144 + c * 16, Vtb + (size_t)r * S_ + c * 8);
        }
    };

    float m0 = -INFINITY, m1 = -INFINITY, l0 = 0.f, l1 = 0.f;
    float oc[8][4] = {};

    loadKV(0, 0);
    cp_commit();

    for (int kt = 0; kt <= ktmax; kt++) {
        __syncthreads();
        int ktn = (kt + 1 <= ktmax) ? kt + 1 : ktmax;
        loadKV((kt + 1) & 1, ktn);
        cp_commit();
        cp_wait1();
        __syncthreads();

        const uint32_t kstg = ksb + (uint32_t)(kt & 1) * KVT_B;
        const uint32_t vstg = vsb + (uint32_t)(kt & 1) * KVT_B;

        float sc[8][4] = {};
#pragma unroll
        for (int kk = 0; kk < 4; kk++) {
            const uint32_t kb = kk * 32;
            uint32_t a0, a1, a2, a3;
            ldsm_x4(a0, a1, a2, a3, qsb + aoff + kb);
            uint32_t bf[8][2];
#pragma unroll
            for (int p = 0; p < 4; p++)
                ldsm_x4(bf[2 * p][0], bf[2 * p][1], bf[2 * p + 1][0], bf[2 * p + 1][1],
                        kstg + boff[p] + kb);
#pragma unroll
            for (int nt = 0; nt < 8; nt++)
                mma_f16(sc[nt], a0, a1, a2, a3, bf[nt][0], bf[nt][1]);
        }

        const bool diag = (kt * 64 + 63 > qt * 128 + wid * 16);
        const int gr0 = qt * 128 + r0;
        const int gc0 = kt * 64 + t * 2;
        float mn0 = m0, mn1 = m1;
#pragma unroll
        for (int nt = 0; nt < 8; nt++) {
#pragma unroll
            for (int j = 0; j < 4; j++) sc[nt][j] *= 0.125f;
            if (diag) {
                int gc = gc0 + nt * 8;
                if (gc     > gr0)     sc[nt][0] = -INFINITY;
                if (gc + 1 > gr0)     sc[nt][1] = -INFINITY;
                if (gc     > gr0 + 8) sc[nt][2] = -INFINITY;
                if (gc + 1 > gr0 + 8) sc[nt][3] = -INFINITY;
            }
            mn0 = fmaxf(mn0, fmaxf(sc[nt][0], sc[nt][1]));
            mn1 = fmaxf(mn1, fmaxf(sc[nt][2], sc[nt][3]));
        }
        mn0 = fmaxf(mn0, __shfl_xor_sync(0xffffffffu, mn0, 1));
        mn0 = fmaxf(mn0, __shfl_xor_sync(0xffffffffu, mn0, 2));
        mn1 = fmaxf(mn1, __shfl_xor_sync(0xffffffffu, mn1, 1));
        mn1 = fmaxf(mn1, __shfl_xor_sync(0xffffffffu, mn1, 2));

        float al0 = __expf(m0 - mn0);
        float al1 = __expf(m1 - mn1);
        m0 = mn0; m1 = mn1;

        float rs0 = 0.f, rs1 = 0.f;
#pragma unroll
        for (int nt = 0; nt < 8; nt++) {
            sc[nt][0] = __expf(sc[nt][0] - mn0);
            sc[nt][1] = __expf(sc[nt][1] - mn0);
            sc[nt][2] = __expf(sc[nt][2] - mn1);
            sc[nt][3] = __expf(sc[nt][3] - mn1);
            rs0 += sc[nt][0] + sc[nt][1];
            rs1 += sc[nt][2] + sc[nt][3];
        }
        rs0 += __shfl_xor_sync(0xffffffffu, rs0, 1);
        rs0 += __shfl_xor_sync(0xffffffffu, rs0, 2);
        rs1 += __shfl_xor_sync(0xffffffffu, rs1, 1);
        rs1 += __shfl_xor_sync(0xffffffffu, rs1, 2);
        l0 = l0 * al0 + rs0;
        l1 = l1 * al1 + rs1;

#pragma unroll
        for (int dt = 0; dt < 8; dt++) {
            oc[dt][0] *= al0; oc[dt][1] *= al0;
            oc[dt][2] *= al1; oc[dt][3] *= al1;
        }

#pragma unroll
        for (int nt = 0; nt < 8; nt++) {
            ((__half2*)Ps)[r0 * FPW_ + nt * 4 + t]       = __floats2half2_rn(sc[nt][0], sc[nt][1]);
            ((__half2*)Ps)[(r0 + 8) * FPW_ + nt * 4 + t] = __floats2half2_rn(sc[nt][2], sc[nt][3]);
        }
        __syncwarp();

#pragma unroll
        for (int kk = 0; kk < 4; kk++) {
            const uint32_t kb = kk * 32;
            uint32_t a0, a1, a2, a3;
            ldsm_x4(a0, a1, a2, a3, psb + aoff + kb);
            uint32_t bf[8][2];
#pragma unroll
            for (int p = 0; p < 4; p++)
                ldsm_x4(bf[2 * p][0], bf[2 * p][1], bf[2 * p + 1][0], bf[2 * p + 1][1],
                        vstg + boff[p] + kb);
#pragma unroll
            for (int dt = 0; dt < 8; dt++)
                mma_f16(oc[dt], a0, a1, a2, a3, bf[dt][0], bf[dt][1]);
        }
    }
    cp_wait0();

    const float inv0 = 1.f / l0;
    const float inv1 = 1.f / l1;
    __half* Ob = Ctx + ((size_t)(b * S_ + qt * 128)) * NQ_ + h * HD_;
#pragma unroll
    for (int dt = 0; dt < 8; dt++) {
        int c = dt * 8 + t * 2;
        *(__half2*)&Ob[(size_t)r0 * NQ_ + c] =
            __floats2half2_rn(oc[dt][0] * inv0, oc[dt][1] * inv0);
        *(__half2*)&Ob[(size_t)(r0 + 8) * NQ_ + c] =
            __floats2half2_rn(oc[dt][2] * inv1, oc[dt][3] * inv1);
    }
}

// ---------------------------------------------------------------------------
// Host launch: fine-grained (per-batch, per-half) software pipeline across
// 4 persistent streams. No allocation/destruction in this function.
// ---------------------------------------------------------------------------
extern "C" void kernel_launch(void* const* d_in, const int* in_sizes, int n_in,
                              void* d_out, int out_size)
{
    const float* x    = (const float*)d_in[0];
    const float* wq   = (const float*)d_in[1];
    const float* wk   = (const float*)d_in[2];
    const float* wv   = (const float*)d_in[3];
    const float* wo   = (const float*)d_in[4];
    const float* cosb = (const float*)d_in[5];
    const float* sinb = (const float*)d_in[6];
    float* out = (float*)d_out;

    __half *xh, *wqt, *wkt, *wvt, *wot, *qh, *kh, *vt, *ctxh;
    cudaGetSymbolAddress((void**)&xh,   g_xh);
    cudaGetSymbolAddress((void**)&wqt,  g_wqt);
    cudaGetSymbolAddress((void**)&wkt,  g_wkt);
    cudaGetSymbolAddress((void**)&wvt,  g_wvt);
    cudaGetSymbolAddress((void**)&wot,  g_wot);
    cudaGetSymbolAddress((void**)&qh,   g_qh);
    cudaGetSymbolAddress((void**)&kh,   g_kh);
    cudaGetSymbolAddress((void**)&vt,   g_vt);
    cudaGetSymbolAddress((void**)&ctxh, g_ctxh);

    const int smem_qkv = NSTG * ST2_B;   // 61440
    const int smem_o   = NSTG * ST_B;    // 81920
    cudaFuncSetAttribute(gemm_qkv, cudaFuncAttributeMaxDynamicSharedMemorySize, smem_qkv);
    cudaFuncSetAttribute(gemm_o,   cudaFuncAttributeMaxDynamicSharedMemorySize, smem_o);
    cudaFuncSetAttribute(flash_h,  cudaFuncAttributeMaxDynamicSharedMemorySize, FSMEM);

    cudaStream_t s1 = g_sc.s1, s2 = g_sc.s2, s3 = g_sc.s3;
    const int HB4 = S_ * D_ / 4;   // fp32x4 elements per batch

    // fork
    cudaEventRecord(g_sc.eFork, 0);
    cudaStreamWaitEvent(s1, g_sc.eFork, 0);
    cudaStreamWaitEvent(s2, g_sc.eFork, 0);
    cudaStreamWaitEvent(s3, g_sc.eFork, 0);

    // prologue
    conv_x<<<(HB4 + 255) / 256, 256, 0, 0>>>(x, xh, HB4);                        // batch 0
    conv_x<<<(HB4 + 255) / 256, 256, 0, s2>>>(x + S_ * D_, xh + S_ * D_, HB4);   // batch 1
    cudaEventRecord(g_sc.eConv1, s2);

    transp<<<dim3(NQ_ / 32, D_ / 32, 1), dim3(32, 8), 0, s1>>>(wq, wq, wqt, wqt, NQ_);
    transp<<<dim3(NKV_ / 32, D_ / 32, 2), dim3(32, 8), 0, s1>>>(wk, wv, wkt, wvt, NKV_);
    cudaEventRecord(g_sc.eTqkv, s1);

    transp<<<dim3(NQ_ / 32, D_ / 32, 1), dim3(32, 8), 0, s2>>>(wo, wo, wot, wot, NQ_);
    cudaEventRecord(g_sc.eWo, s2);

    // ---- QKV chunks ----
    // batch 0 on s0 (default): after conv_x(b0) [stream order] + eTqkv
    cudaStreamWaitEvent(0, g_sc.eTqkv, 0);
    gemm_qkv<<<dim3(48, 4), 128, smem_qkv, 0>>>(xh, wqt, wkt, wvt, cosb, sinb, 0);
    cudaEventRecord(g_sc.eQ00, 0);
    gemm_qkv<<<dim3(48, 4), 128, smem_qkv, 0>>>(xh, wqt, wkt, wvt, cosb, sinb, 512);
    cudaEventRecord(g_sc.eQ01, 0);

    // batch 1 on s1: after transp (stream order) + conv_x(b1)
    cudaStreamWaitEvent(s1, g_sc.eConv1, 0);
    gemm_qkv<<<dim3(48, 4), 128, smem_qkv, s1>>>(xh, wqt, wkt, wvt, cosb, sinb, S_);
    cudaEventRecord(g_sc.eQ10, s1);
    gemm_qkv<<<dim3(48, 4), 128, smem_qkv, s1>>>(xh, wqt, wkt, wvt, cosb, sinb, S_ + 512);
    cudaEventRecord(g_sc.eQ11, s1);

    // ---- flash chunks ----
    // batch 0 on s3
    cudaStreamWaitEvent(s3, g_sc.eQ00, 0);
    flash_h<<<dim3(4, 32), 256, FSMEM, s3>>>(qh, kh, vt, ctxh, 0, 0);
    cudaEventRecord(g_sc.eF00, s3);
    cudaStreamWaitEvent(s3, g_sc.eQ01, 0);
    flash_h<<<dim3(4, 32), 256, FSMEM, s3>>>(qh, kh, vt, ctxh, 0, 4);
    cudaEventRecord(g_sc.eF01, s3);

    // batch 1 on s2 (after transp_wo, stream order)
    cudaStreamWaitEvent(s2, g_sc.eQ10, 0);
    flash_h<<<dim3(4, 32), 256, FSMEM, s2>>>(qh, kh, vt, ctxh, 1, 0);
    cudaEventRecord(g_sc.eF10, s2);
    cudaStreamWaitEvent(s2, g_sc.eQ11, 0);
    flash_h<<<dim3(4, 32), 256, FSMEM, s2>>>(qh, kh, vt, ctxh, 1, 4);
    cudaEventRecord(g_sc.eF11, s2);

    // ---- O-proj chunks ----
    // batch 0 on s0
    cudaStreamWaitEvent(0, g_sc.eF00, 0);
    cudaStreamWaitEvent(0, g_sc.eWo, 0);
    gemm_o<<<dim3(16, 4), 128, smem_o, 0>>>(ctxh, wot, out, 0);
    cudaStreamWaitEvent(0, g_sc.eF01, 0);
    gemm_o<<<dim3(16, 4), 128, smem_o, 0>>>(ctxh, wot, out, 512);

    // batch 1 on s1
    cudaStreamWaitEvent(s1, g_sc.eF10, 0);
    cudaStreamWaitEvent(s1, g_sc.eWo, 0);
    gemm_o<<<dim3(16, 4), 128, smem_o, s1>>>(ctxh, wot, out, S_);
    cudaStreamWaitEvent(s1, g_sc.eF11, 0);
    gemm_o<<<dim3(16, 4), 128, smem_o, s1>>>(ctxh, wot, out, S_ + 512);
    cudaEventRecord(g_sc.eB1, s1);

    // join (s2 drains into s1 via eF11; s3 drains into s0 via eF01)
    cudaStreamWaitEvent(0, g_sc.eB1, 0);
}

// round 12
// speedup vs baseline: 1.0609x; 1.0609x over previous
#include <cuda_runtime.h>
#include <cuda_fp16.h>
#include <math.h>
#include <stdint.h>

#define B_    2
#define S_    1024
#define D_    2048
#define H_    32
#define HKV_  8
#define HD_   64
#define REP_  4
#define M_    (B_ * S_)       // 2048
#define NQ_   (H_ * HD_)      // 2048
#define NKV_  (HKV_ * HD_)    // 512

// ---------------------------------------------------------------------------
// Device-global scratch (no cudaMalloc allowed)
// ---------------------------------------------------------------------------
__device__ __half g_xh [M_ * D_];
__device__ __half g_wqt[NQ_ * D_];     // wq^T  [N][K]
__device__ __half g_wkt[NKV_ * D_];
__device__ __half g_wvt[NKV_ * D_];
__device__ __half g_wot[D_ * NQ_];     // wo^T
__device__ __half g_qh [M_ * NQ_];     // q (rope applied)
__device__ __half g_kh [M_ * NKV_];    // k (rope applied)
__device__ __half g_vt [B_ * HKV_ * HD_ * S_];  // v transposed: [b][gh][d][s]
__device__ __half g_ctxh[M_ * NQ_];

// ---------------------------------------------------------------------------
// Persistent streams/events (created once pre-main; never in kernel_launch)
// ---------------------------------------------------------------------------
struct StreamCtx {
    cudaStream_t s1, s2;
    cudaEvent_t  eFork, eConv, eTqkv, eWo, eC1;
    StreamCtx() {
        cudaStreamCreateWithFlags(&s1, cudaStreamNonBlocking);
        cudaStreamCreateWithFlags(&s2, cudaStreamNonBlocking);
        cudaEventCreateWithFlags(&eFork, cudaEventDisableTiming);
        cudaEventCreateWithFlags(&eConv, cudaEventDisableTiming);
        cudaEventCreateWithFlags(&eTqkv, cudaEventDisableTiming);
        cudaEventCreateWithFlags(&eWo,   cudaEventDisableTiming);
        cudaEventCreateWithFlags(&eC1,   cudaEventDisableTiming);
    }
};
static StreamCtx g_sc;

// ---------------------------------------------------------------------------
// device helpers
// ---------------------------------------------------------------------------
__device__ __forceinline__ void mma_f16(float* c,
        uint32_t a0, uint32_t a1, uint32_t a2, uint32_t a3,
        uint32_t b0, uint32_t b1) {
    asm volatile(
        "mma.sync.aligned.m16n8k16.row.col.f32.f16.f16.f32 "
        "{%0,%1,%2,%3}, {%4,%5,%6,%7}, {%8,%9}, {%0,%1,%2,%3};"
        : "+f"(c[0]), "+f"(c[1]), "+f"(c[2]), "+f"(c[3])
        : "r"(a0), "r"(a1), "r"(a2), "r"(a3), "r"(b0), "r"(b1));
}

__device__ __forceinline__ void ldsm_x4(uint32_t& r0, uint32_t& r1,
                                        uint32_t& r2, uint32_t& r3, uint32_t addr) {
    asm volatile("ldmatrix.sync.aligned.m8n8.x4.shared.b16 {%0,%1,%2,%3}, [%4];"
                 : "=r"(r0), "=r"(r1), "=r"(r2), "=r"(r3) : "r"(addr));
}

__device__ __forceinline__ void cp16(uint32_t saddr, const void* gptr) {
    asm volatile("cp.async.cg.shared.global [%0], [%1], 16;"
                 :: "r"(saddr), "l"(gptr) : "memory");
}
__device__ __forceinline__ void cp_commit() {
    asm volatile("cp.async.commit_group;" ::: "memory");
}
__device__ __forceinline__ void cp_wait2() {
    asm volatile("cp.async.wait_group 2;" ::: "memory");
}
__device__ __forceinline__ void cp_wait1() {
    asm volatile("cp.async.wait_group 1;" ::: "memory");
}
__device__ __forceinline__ void cp_wait0() {
    asm volatile("cp.async.wait_group 0;" ::: "memory");
}

// ---------------------------------------------------------------------------
// Converters
// ---------------------------------------------------------------------------
__global__ void conv_x(const float* __restrict__ x, __half* __restrict__ xh, int n4)
{
    int i = blockIdx.x * 256 + threadIdx.x;
    if (i >= n4) return;
    float4 v = ((const float4*)x)[i];
    ((__half2*)xh)[i * 2]     = __floats2half2_rn(v.x, v.y);
    ((__half2*)xh)[i * 2 + 1] = __floats2half2_rn(v.z, v.w);
}

__global__ void transp(const float* __restrict__ s0, const float* __restrict__ s1,
                       __half* __restrict__ d0, __half* __restrict__ d1, int N)
{
    const float* src = blockIdx.z ? s1 : s0;
    __half*      dst = blockIdx.z ? d1 : d0;
    __shared__ float t[32][33];
    int n0 = blockIdx.x * 32, k0 = blockIdx.y * 32;
    int x = threadIdx.x, y = threadIdx.y;
#pragma unroll
    for (int j = 0; j < 32; j += 8)
        t[y + j][x] = src[(size_t)(k0 + y + j) * N + n0 + x];
    __syncthreads();
#pragma unroll
    for (int j = 0; j < 32; j += 8)
        dst[(size_t)(n0 + y + j) * D_ + k0 + x] = __float2half(t[x][y + j]);
}

// ---------------------------------------------------------------------------
// QKV GEMM: 128x64 CTA tiles, 4 warps (warp tile 32x64), cp.async 4-stage.
// Per-batch: grid (48, 8), mbase selects batch rows.
// ---------------------------------------------------------------------------
#define GP     40
#define A2_B   (128 * GP * 2)
#define ST2_B  (192 * GP * 2)
#define NSTG   4
#define NITER  (D_ / 32)

__global__ __launch_bounds__(128, 3) void gemm_qkv(
    const __half* __restrict__ A,
    const __half* __restrict__ W0, const __half* __restrict__ W1,
    const __half* __restrict__ W2,
    const float* __restrict__ cosb, const float* __restrict__ sinb,
    int mbase)
{
    extern __shared__ __half sh[];
    const int bx = blockIdx.x, by = blockIdx.y;
    const int tid = threadIdx.x, lane = tid & 31, wid = tid >> 5;
    const int g = lane >> 2, t = lane & 3;
    const int wm = wid * 32;

    const __half* Wt;
    int ctile, sel;
    if (bx < 32)      { Wt = W0; ctile = bx;      sel = 0; }
    else if (bx < 40) { Wt = W1; ctile = bx - 32; sel = 1; }
    else              { Wt = W2; ctile = bx - 40; sel = 2; }

    const __half* Ab = A  + (size_t)(mbase + by * 128) * D_;
    const __half* Bb = Wt + (size_t)ctile * 64 * D_;

    const uint32_t sbase = (uint32_t)__cvta_generic_to_shared(sh);

    auto issue = [&](int stage, int k0) {
        uint32_t sa = sbase + stage * ST2_B;
#pragma unroll
        for (int j = 0; j < 4; j++) {
            int idx = tid + j * 128;
            int r = idx >> 2, c = idx & 3;
            cp16(sa + (r * GP + c * 8) * 2, Ab + (size_t)r * D_ + k0 + c * 8);
        }
#pragma unroll
        for (int j = 0; j < 2; j++) {
            int idx = tid + j * 128;
            int r = idx >> 2, c = idx & 3;
            cp16(sa + A2_B + (r * GP + c * 8) * 2, Bb + (size_t)r * D_ + k0 + c * 8);
        }
    };

    uint32_t aoff[2], boff[4];
#pragma unroll
    for (int mt = 0; mt < 2; mt++)
        aoff[mt] = ((wm + mt * 16 + (lane & 7) + ((lane >> 3) & 1) * 8) * GP
                    + (lane >> 4) * 8) * 2;
#pragma unroll
    for (int p = 0; p < 4; p++)
        boff[p] = (uint32_t)A2_B +
                  ((p * 16 + (lane & 7) + ((lane >> 4) & 1) * 8) * GP
                   + ((lane >> 3) & 1) * 8) * 2;

    float acc[2][8][4] = {};

    issue(0, 0);  cp_commit();
    issue(1, 32); cp_commit();
    issue(2, 64); cp_commit();

    for (int it = 0; it < NITER; ++it) {
        cp_wait2();
        __syncthreads();
        if (it + 3 < NITER) issue((it + 3) & 3, (it + 3) * 32);
        cp_commit();

        const uint32_t sstg = sbase + (uint32_t)(it & 3) * ST2_B;
#pragma unroll
        for (int kk = 0; kk < 2; kk++) {
            const uint32_t kb = kk * 32;
            uint32_t af[2][4];
#pragma unroll
            for (int mt = 0; mt < 2; mt++)
                ldsm_x4(af[mt][0], af[mt][1], af[mt][2], af[mt][3],
                        sstg + aoff[mt] + kb);
            uint32_t bf[8][2];
#pragma unroll
            for (int p = 0; p < 4; p++)
                ldsm_x4(bf[2 * p][0], bf[2 * p][1], bf[2 * p + 1][0], bf[2 * p + 1][1],
                        sstg + boff[p] + kb);
#pragma unroll
            for (int mt = 0; mt < 2; mt++)
#pragma unroll
                for (int nt = 0; nt < 8; nt++)
                    mma_f16(acc[mt][nt], af[mt][0], af[mt][1], af[mt][2], af[mt][3],
                            bf[nt][0], bf[nt][1]);
        }
    }

#pragma unroll
    for (int mt = 0; mt < 2; mt++) {
        const int r0g = mbase + by * 128 + wm + mt * 16 + g;
        const int r1g = r0g + 8;

        if (sel == 2) {
            int b0 = r0g >> 10, s0 = r0g & (S_ - 1);
            int b1 = r1g >> 10, s1 = r1g & (S_ - 1);
#pragma unroll
            for (int nt = 0; nt < 8; nt++) {
                int colk = ctile * 64 + nt * 8 + t * 2;
                int gh = colk >> 6, d = colk & 63;
                size_t base0 = ((size_t)(b0 * HKV_ + gh) * HD_) * S_;
                size_t base1 = ((size_t)(b1 * HKV_ + gh) * HD_) * S_;
                g_vt[base0 + (size_t)d * S_ + s0]       = __float2half(acc[mt][nt][0]);
                g_vt[base0 + (size_t)(d + 1) * S_ + s0] = __float2half(acc[mt][nt][1]);
                g_vt[base1 + (size_t)d * S_ + s1]       = __float2half(acc[mt][nt][2]);
                g_vt[base1 + (size_t)(d + 1) * S_ + s1] = __float2half(acc[mt][nt][3]);
            }
        } else {
            int s0 = r0g & (S_ - 1), s1 = r1g & (S_ - 1);
#pragma unroll
            for (int nt = 0; nt < 4; nt++) {
                int d = nt * 8 + 2 * t;
                float c0a = cosb[s0 * HD_ + d], c0b = cosb[s0 * HD_ + d + 1];
                float z0a = sinb[s0 * HD_ + d], z0b = sinb[s0 * HD_ + d + 1];
                float c1a = cosb[s1 * HD_ + d], c1b = cosb[s1 * HD_ + d + 1];
                float z1a = sinb[s1 * HD_ + d], z1b = sinb[s1 * HD_ + d + 1];
                float a, b;
                a = acc[mt][nt][0]; b = acc[mt][nt + 4][0];
                acc[mt][nt][0] = a * c0a - b * z0a;  acc[mt][nt + 4][0] = b * c0a + a * z0a;
                a = acc[mt][nt][1]; b = acc[mt][nt + 4][1];
                acc[mt][nt][1] = a * c0b - b * z0b;  acc[mt][nt + 4][1] = b * c0b + a * z0b;
                a = acc[mt][nt][2]; b = acc[mt][nt + 4][2];
                acc[mt][nt][2] = a * c1a - b * z1a;  acc[mt][nt + 4][2] = b * c1a + a * z1a;
                a = acc[mt][nt][3]; b = acc[mt][nt + 4][3];
                acc[mt][nt][3] = a * c1b - b * z1b;  acc[mt][nt + 4][3] = b * c1b + a * z1b;
            }
            __half* dst = (sel == 0) ? g_qh : g_kh;
            const int pitch = (sel == 0) ? NQ_ : NKV_;
            const int cb = ctile * 64;
#pragma unroll
            for (int nt = 0; nt < 8; nt++) {
                int col = cb + nt * 8 + t * 2;
                *(__half2*)&dst[(size_t)r0g * pitch + col] =
                    __floats2half2_rn(acc[mt][nt][0], acc[mt][nt][1]);
                *(__half2*)&dst[(size_t)r1g * pitch + col] =
                    __floats2half2_rn(acc[mt][nt][2], acc[mt][nt][3]);
            }
        }
    }
}

// ---------------------------------------------------------------------------
// O-projection GEMM: 128x128 CTA tiles, per-batch grid (16, 8).
// ---------------------------------------------------------------------------
#define ST_B  (2 * 128 * GP * 2)
#define AB_B  (128 * GP * 2)

__global__ __launch_bounds__(128, 2) void gemm_o(
    const __half* __restrict__ A,
    const __half* __restrict__ W0,
    float* __restrict__ Cf, int mbase)
{
    extern __shared__ __half sh[];
    const int bx = blockIdx.x, by = blockIdx.y;
    const int tid = threadIdx.x, lane = tid & 31, wid = tid >> 5;
    const int g = lane >> 2, t = lane & 3;
    const int wm = (wid & 1) * 64, wn = (wid >> 1) * 64;

    const __half* Ab = A  + (size_t)(mbase + by * 128) * D_;
    const __half* Bb = W0 + (size_t)bx * 128 * D_;

    const uint32_t sbase = (uint32_t)__cvta_generic_to_shared(sh);

    auto issue = [&](int stage, int k0) {
        uint32_t sa = sbase + stage * ST_B;
#pragma unroll
        for (int j = 0; j < 4; j++) {
            int idx = tid + j * 128;
            int r = idx >> 2, c = idx & 3;
            cp16(sa +        (r * GP + c * 8) * 2, Ab + (size_t)r * D_ + k0 + c * 8);
            cp16(sa + AB_B + (r * GP + c * 8) * 2, Bb + (size_t)r * D_ + k0 + c * 8);
        }
    };

    uint32_t aoff[4], boff[4];
#pragma unroll
    for (int mt = 0; mt < 4; mt++)
        aoff[mt] = ((wm + mt * 16 + (lane & 7) + ((lane >> 3) & 1) * 8) * GP
                    + (lane >> 4) * 8) * 2;
#pragma unroll
    for (int p = 0; p < 4; p++)
        boff[p] = (uint32_t)AB_B +
                  ((wn + p * 16 + (lane & 7) + ((lane >> 4) & 1) * 8) * GP
                   + ((lane >> 3) & 1) * 8) * 2;

    float acc[4][8][4] = {};

    issue(0, 0);  cp_commit();
    issue(1, 32); cp_commit();
    issue(2, 64); cp_commit();

    for (int it = 0; it < NITER; ++it) {
        cp_wait2();
        __syncthreads();
        if (it + 3 < NITER) issue((it + 3) & 3, (it + 3) * 32);
        cp_commit();

        const uint32_t sstg = sbase + (uint32_t)(it & 3) * ST_B;
#pragma unroll
        for (int kk = 0; kk < 2; kk++) {
            const uint32_t kb = kk * 32;
            uint32_t af[4][4];
#pragma unroll
            for (int mt = 0; mt < 4; mt++)
                ldsm_x4(af[mt][0], af[mt][1], af[mt][2], af[mt][3],
                        sstg + aoff[mt] + kb);
            uint32_t bf[8][2];
#pragma unroll
            for (int p = 0; p < 4; p++)
                ldsm_x4(bf[2 * p][0], bf[2 * p][1], bf[2 * p + 1][0], bf[2 * p + 1][1],
                        sstg + boff[p] + kb);
#pragma unroll
            for (int mt = 0; mt < 4; mt++)
#pragma unroll
                for (int nt = 0; nt < 8; nt++)
                    mma_f16(acc[mt][nt], af[mt][0], af[mt][1], af[mt][2], af[mt][3],
                            bf[nt][0], bf[nt][1]);
        }
    }

#pragma unroll
    for (int mt = 0; mt < 4; mt++) {
        const int r0g = mbase + by * 128 + wm + mt * 16 + g;
        const int r1g = r0g + 8;
#pragma unroll
        for (int nt = 0; nt < 8; nt++) {
            int col = bx * 128 + wn + nt * 8 + t * 2;
            *(float2*)&Cf[(size_t)r0g * NQ_ + col] =
                make_float2(acc[mt][nt][0], acc[mt][nt][1]);
            *(float2*)&Cf[(size_t)r1g * NQ_ + col] =
                make_float2(acc[mt][nt][2], acc[mt][nt][3]);
        }
    }
}

// ---------------------------------------------------------------------------
// Flash attention with BALANCED TILE PAIRING:
// grid (4, 32) per batch; CTA x processes q-tiles {x, 7-x} sequentially, so
// every CTA does exactly 18 k-iterations (causal tail eliminated).
// 128 q-rows per tile, 8 warps, cp.async double-buffered K/V.
// ---------------------------------------------------------------------------
#define FP_   72
#define FPW_  36
#define KVT_B (64 * FP_ * 2)
#define FQ_OFF 0
#define FK_OFF 18432
#define FV_OFF 36864
#define FPOFF  55296
#define FSMEM  73728

__global__ __launch_bounds__(256) void flash_h(
    const __half* __restrict__ Q,
    const __half* __restrict__ K,
    const __half* __restrict__ Vt,
    __half* __restrict__ Ctx, int b)
{
    extern __shared__ __half fsh[];
    const uint32_t sb  = (uint32_t)__cvta_generic_to_shared(fsh);
    const uint32_t qsb = sb + FQ_OFF;
    const uint32_t ksb = sb + FK_OFF;
    const uint32_t vsb = sb + FV_OFF;
    const uint32_t psb = sb + FPOFF;
    __half* Ps = fsh + FPOFF / 2;

    const int h   = blockIdx.y;
    const int gh  = h / REP_;
    const int tid = threadIdx.x;
    const int lane = tid & 31;
    const int wid  = tid >> 5;
    const int g    = lane >> 2;
    const int t    = lane & 3;
    const int r0   = wid * 16 + g;

    const uint32_t aoff = ((wid * 16 + (lane & 7) + ((lane >> 3) & 1) * 8) * FP_
                           + (lane >> 4) * 8) * 2;
    uint32_t boff[4];
#pragma unroll
    for (int p = 0; p < 4; p++)
        boff[p] = ((p * 16 + (lane & 7) + ((lane >> 4) & 1) * 8) * FP_
                   + ((lane >> 3) & 1) * 8) * 2;

    const __half* Kbase  = K  + ((size_t)(b * S_)) * NKV_ + gh * HD_;
    const __half* Vtbase = Vt + ((size_t)(b * HKV_ + gh)) * HD_ * S_;
    auto loadKV = [&](int st, int kt) {
        uint32_t kst = ksb + st * KVT_B;
        uint32_t vst = vsb + st * KVT_B;
        const __half* Kb  = Kbase  + (size_t)(kt * 64) * NKV_;
        const __half* Vtb = Vtbase + kt * 64;
#pragma unroll
        for (int j = 0; j < 2; j++) {
            int idx = tid + j * 256;
            int r = idx >> 3, c = idx & 7;
            cp16(kst + r * 144 + c * 16, Kb  + (size_t)r * NKV_ + c * 8);
            cp16(vst + r * 144 + c * 16, Vtb + (size_t)r * S_ + c * 8);
        }
    };

    // two balanced tiles: work(x) + work(7-x) = 18 k-iterations for all x
#pragma unroll 1
    for (int half = 0; half < 2; half++) {
        const int qt = (half == 0) ? (int)blockIdx.x : 7 - (int)blockIdx.x;
        const int ktmax = 2 * qt + 1;

        // ensure all warps are done reading previous tile's smem
        __syncthreads();

        // load Q tile (128 x 64)
        const __half* Qb = Q + ((size_t)(b * S_ + qt * 128)) * NQ_ + h * HD_;
#pragma unroll
        for (int j = 0; j < 4; j++) {
            int idx = tid + j * 256;
            int r = idx >> 3, c = (idx & 7) * 8;
            *(uint4*)&fsh[(FQ_OFF / 2) + r * FP_ + c] =
                *(const uint4*)(Qb + (size_t)r * NQ_ + c);
        }

        float m0 = -INFINITY, m1 = -INFINITY, l0 = 0.f, l1 = 0.f;
        float oc[8][4] = {};

        loadKV(0, 0);
        cp_commit();

        for (int kt = 0; kt <= ktmax; kt++) {
            __syncthreads();
            int ktn = (kt + 1 <= ktmax) ? kt + 1 : ktmax;
            loadKV((kt + 1) & 1, ktn);
            cp_commit();
            cp_wait1();
            __syncthreads();

            const uint32_t kstg = ksb + (uint32_t)(kt & 1) * KVT_B;
            const uint32_t vstg = vsb + (uint32_t)(kt & 1) * KVT_B;

            float sc[8][4] = {};
#pragma unroll
            for (int kk = 0; kk < 4; kk++) {
                const uint32_t kb = kk * 32;
                uint32_t a0, a1, a2, a3;
                ldsm_x4(a0, a1, a2, a3, qsb + aoff + kb);
                uint32_t bf[8][2];
#pragma unroll
                for (int p = 0; p < 4; p++)
                    ldsm_x4(bf[2 * p][0], bf[2 * p][1], bf[2 * p + 1][0], bf[2 * p + 1][1],
                            kstg + boff[p] + kb);
#pragma unroll
                for (int nt = 0; nt < 8; nt++)
                    mma_f16(sc[nt], a0, a1, a2, a3, bf[nt][0], bf[nt][1]);
            }

            const bool diag = (kt * 64 + 63 > qt * 128 + wid * 16);
            const int gr0 = qt * 128 + r0;
            const int gc0 = kt * 64 + t * 2;
            float mn0 = m0, mn1 = m1;
#pragma unroll
            for (int nt = 0; nt < 8; nt++) {
#pragma unroll
                for (int j = 0; j < 4; j++) sc[nt][j] *= 0.125f;
                if (diag) {
                    int gc = gc0 + nt * 8;
                    if (gc     > gr0)     sc[nt][0] = -INFINITY;
                    if (gc + 1 > gr0)     sc[nt][1] = -INFINITY;
                    if (gc     > gr0 + 8) sc[nt][2] = -INFINITY;
                    if (gc + 1 > gr0 + 8) sc[nt][3] = -INFINITY;
                }
                mn0 = fmaxf(mn0, fmaxf(sc[nt][0], sc[nt][1]));
                mn1 = fmaxf(mn1, fmaxf(sc[nt][2], sc[nt][3]));
            }
            mn0 = fmaxf(mn0, __shfl_xor_sync(0xffffffffu, mn0, 1));
            mn0 = fmaxf(mn0, __shfl_xor_sync(0xffffffffu, mn0, 2));
            mn1 = fmaxf(mn1, __shfl_xor_sync(0xffffffffu, mn1, 1));
            mn1 = fmaxf(mn1, __shfl_xor_sync(0xffffffffu, mn1, 2));

            float al0 = __expf(m0 - mn0);
            float al1 = __expf(m1 - mn1);
            m0 = mn0; m1 = mn1;

            float rs0 = 0.f, rs1 = 0.f;
#pragma unroll
            for (int nt = 0; nt < 8; nt++) {
                sc[nt][0] = __expf(sc[nt][0] - mn0);
                sc[nt][1] = __expf(sc[nt][1] - mn0);
                sc[nt][2] = __expf(sc[nt][2] - mn1);
                sc[nt][3] = __expf(sc[nt][3] - mn1);
                rs0 += sc[nt][0] + sc[nt][1];
                rs1 += sc[nt][2] + sc[nt][3];
            }
            rs0 += __shfl_xor_sync(0xffffffffu, rs0, 1);
            rs0 += __shfl_xor_sync(0xffffffffu, rs0, 2);
            rs1 += __shfl_xor_sync(0xffffffffu, rs1, 1);
            rs1 += __shfl_xor_sync(0xffffffffu, rs1, 2);
            l0 = l0 * al0 + rs0;
            l1 = l1 * al1 + rs1;

#pragma unroll
            for (int dt = 0; dt < 8; dt++) {
                oc[dt][0] *= al0; oc[dt][1] *= al0;
                oc[dt][2] *= al1; oc[dt][3] *= al1;
            }

#pragma unroll
            for (int nt = 0; nt < 8; nt++) {
                ((__half2*)Ps)[r0 * FPW_ + nt * 4 + t]       = __floats2half2_rn(sc[nt][0], sc[nt][1]);
                ((__half2*)Ps)[(r0 + 8) * FPW_ + nt * 4 + t] = __floats2half2_rn(sc[nt][2], sc[nt][3]);
            }
            __syncwarp();

#pragma unroll
            for (int kk = 0; kk < 4; kk++) {
                const uint32_t kb = kk * 32;
                uint32_t a0, a1, a2, a3;
                ldsm_x4(a0, a1, a2, a3, psb + aoff + kb);
                uint32_t bf[8][2];
#pragma unroll
                for (int p = 0; p < 4; p++)
                    ldsm_x4(bf[2 * p][0], bf[2 * p][1], bf[2 * p + 1][0], bf[2 * p + 1][1],
                            vstg + boff[p] + kb);
#pragma unroll
                for (int dt = 0; dt < 8; dt++)
                    mma_f16(oc[dt], a0, a1, a2, a3, bf[dt][0], bf[dt][1]);
            }
        }
        cp_wait0();

        const float inv0 = 1.f / l0;
        const float inv1 = 1.f / l1;
        __half* Ob = Ctx + ((size_t)(b * S_ + qt * 128)) * NQ_ + h * HD_;
#pragma unroll
        for (int dt = 0; dt < 8; dt++) {
            int c = dt * 8 + t * 2;
            *(__half2*)&Ob[(size_t)r0 * NQ_ + c] =
                __floats2half2_rn(oc[dt][0] * inv0, oc[dt][1] * inv0);
            *(__half2*)&Ob[(size_t)(r0 + 8) * NQ_ + c] =
                __floats2half2_rn(oc[dt][2] * inv1, oc[dt][3] * inv1);
        }
    }
}

// ---------------------------------------------------------------------------
// Host launch: R10's forked-stream DAG (persistent streams, no allocation).
// ---------------------------------------------------------------------------
extern "C" void kernel_launch(void* const* d_in, const int* in_sizes, int n_in,
                              void* d_out, int out_size)
{
    const float* x    = (const float*)d_in[0];
    const float* wq   = (const float*)d_in[1];
    const float* wk   = (const float*)d_in[2];
    const float* wv   = (const float*)d_in[3];
    const float* wo   = (const float*)d_in[4];
    const float* cosb = (const float*)d_in[5];
    const float* sinb = (const float*)d_in[6];
    float* out = (float*)d_out;

    __half *xh, *wqt, *wkt, *wvt, *wot, *qh, *kh, *vt, *ctxh;
    cudaGetSymbolAddress((void**)&xh,   g_xh);
    cudaGetSymbolAddress((void**)&wqt,  g_wqt);
    cudaGetSymbolAddress((void**)&wkt,  g_wkt);
    cudaGetSymbolAddress((void**)&wvt,  g_wvt);
    cudaGetSymbolAddress((void**)&wot,  g_wot);
    cudaGetSymbolAddress((void**)&qh,   g_qh);
    cudaGetSymbolAddress((void**)&kh,   g_kh);
    cudaGetSymbolAddress((void**)&vt,   g_vt);
    cudaGetSymbolAddress((void**)&ctxh, g_ctxh);

    const int smem_qkv = NSTG * ST2_B;   // 61440
    const int smem_o   = NSTG * ST_B;    // 81920
    cudaFuncSetAttribute(gemm_qkv, cudaFuncAttributeMaxDynamicSharedMemorySize, smem_qkv);
    cudaFuncSetAttribute(gemm_o,   cudaFuncAttributeMaxDynamicSharedMemorySize, smem_o);
    cudaFuncSetAttribute(flash_h,  cudaFuncAttributeMaxDynamicSharedMemorySize, FSMEM);

    cudaStream_t s1 = g_sc.s1, s2 = g_sc.s2;

    // fork
    cudaEventRecord(g_sc.eFork, 0);
    cudaStreamWaitEvent(s1, g_sc.eFork, 0);
    cudaStreamWaitEvent(s2, g_sc.eFork, 0);

    // prologue
    conv_x<<<(M_ * D_ / 4 + 255) / 256, 256, 0, 0>>>(x, xh, M_ * D_ / 4);
    cudaEventRecord(g_sc.eConv, 0);

    transp<<<dim3(NQ_ / 32, D_ / 32, 1), dim3(32, 8), 0, s1>>>(wq, wq, wqt, wqt, NQ_);
    transp<<<dim3(NKV_ / 32, D_ / 32, 2), dim3(32, 8), 0, s1>>>(wk, wv, wkt, wvt, NKV_);
    cudaEventRecord(g_sc.eTqkv, s1);

    transp<<<dim3(NQ_ / 32, D_ / 32, 1), dim3(32, 8), 0, s2>>>(wo, wo, wot, wot, NQ_);
    cudaEventRecord(g_sc.eWo, s2);

    // chain b0 on default stream (has eConv implicitly; needs eTqkv)
    cudaStreamWaitEvent(0, g_sc.eTqkv, 0);
    gemm_qkv<<<dim3(48, 8), 128, smem_qkv, 0>>>(xh, wqt, wkt, wvt, cosb, sinb, 0);
    flash_h<<<dim3(4, 32), 256, FSMEM, 0>>>(qh, kh, vt, ctxh, 0);
    cudaStreamWaitEvent(0, g_sc.eWo, 0);
    gemm_o<<<dim3(16, 8), 128, smem_o, 0>>>(ctxh, wot, out, 0);

    // chain b1 on s1 (has eTqkv implicitly; needs eConv)
    cudaStreamWaitEvent(s1, g_sc.eConv, 0);
    gemm_qkv<<<dim3(48, 8), 128, smem_qkv, s1>>>(xh, wqt, wkt, wvt, cosb, sinb, S_);
    flash_h<<<dim3(4, 32), 256, FSMEM, s1>>>(qh, kh, vt, ctxh, 1);
    cudaStreamWaitEvent(s1, g_sc.eWo, 0);
    gemm_o<<<dim3(16, 8), 128, smem_o, s1>>>(ctxh, wot, out, S_);
    cudaEventRecord(g_sc.eC1, s1);

    // join
    cudaStreamWaitEvent(0, g_sc.eC1, 0);
}

// round 13
// speedup vs baseline: 1.0816x; 1.0196x over previous
#include <cuda_runtime.h>
#include <cuda_fp16.h>
#include <math.h>
#include <stdint.h>

#define B_    2
#define S_    1024
#define D_    2048
#define H_    32
#define HKV_  8
#define HD_   64
#define REP_  4
#define M_    (B_ * S_)       // 2048
#define NQ_   (H_ * HD_)      // 2048
#define NKV_  (HKV_ * HD_)    // 512

// ---------------------------------------------------------------------------
// Device-global scratch (no cudaMalloc allowed)
// ---------------------------------------------------------------------------
__device__ __half g_xh [M_ * D_];
__device__ __half g_wqt[NQ_ * D_];
__device__ __half g_wkt[NKV_ * D_];
__device__ __half g_wvt[NKV_ * D_];
__device__ __half g_wot[D_ * NQ_];
__device__ __half g_qh [M_ * NQ_];
__device__ __half g_kh [M_ * NKV_];
__device__ __half g_vt [B_ * HKV_ * HD_ * S_];   // [b][gh][d][s]
__device__ __half g_ctxh[M_ * NQ_];

// ---------------------------------------------------------------------------
// Persistent streams/events (created once pre-main; never in kernel_launch)
// ---------------------------------------------------------------------------
struct StreamCtx {
    cudaStream_t s1, s2, s3;
    cudaEvent_t  eFork, eTwq, eTwkv, eWo, eConv1, eC1;
    StreamCtx() {
        cudaStreamCreateWithFlags(&s1, cudaStreamNonBlocking);
        cudaStreamCreateWithFlags(&s2, cudaStreamNonBlocking);
        cudaStreamCreateWithFlags(&s3, cudaStreamNonBlocking);
        cudaEvent_t* evs[] = {&eFork, &eTwq, &eTwkv, &eWo, &eConv1, &eC1};
        for (auto e : evs) cudaEventCreateWithFlags(e, cudaEventDisableTiming);
    }
};
static StreamCtx g_sc;

// ---------------------------------------------------------------------------
// device helpers
// ---------------------------------------------------------------------------
__device__ __forceinline__ void mma_f16(float* c,
        uint32_t a0, uint32_t a1, uint32_t a2, uint32_t a3,
        uint32_t b0, uint32_t b1) {
    asm volatile(
        "mma.sync.aligned.m16n8k16.row.col.f32.f16.f16.f32 "
        "{%0,%1,%2,%3}, {%4,%5,%6,%7}, {%8,%9}, {%0,%1,%2,%3};"
        : "+f"(c[0]), "+f"(c[1]), "+f"(c[2]), "+f"(c[3])
        : "r"(a0), "r"(a1), "r"(a2), "r"(a3), "r"(b0), "r"(b1));
}

__device__ __forceinline__ void ldsm_x4(uint32_t& r0, uint32_t& r1,
                                        uint32_t& r2, uint32_t& r3, uint32_t addr) {
    asm volatile("ldmatrix.sync.aligned.m8n8.x4.shared.b16 {%0,%1,%2,%3}, [%4];"
                 : "=r"(r0), "=r"(r1), "=r"(r2), "=r"(r3) : "r"(addr));
}

__device__ __forceinline__ void cp16(uint32_t saddr, const void* gptr) {
    asm volatile("cp.async.cg.shared.global [%0], [%1], 16;"
                 :: "r"(saddr), "l"(gptr) : "memory");
}
__device__ __forceinline__ void cp_commit() {
    asm volatile("cp.async.commit_group;" ::: "memory");
}
__device__ __forceinline__ void cp_wait2() {
    asm volatile("cp.async.wait_group 2;" ::: "memory");
}
__device__ __forceinline__ void cp_wait1() {
    asm volatile("cp.async.wait_group 1;" ::: "memory");
}
__device__ __forceinline__ void cp_wait0() {
    asm volatile("cp.async.wait_group 0;" ::: "memory");
}

// ---------------------------------------------------------------------------
// Converters
// ---------------------------------------------------------------------------
__global__ void conv_x(const float* __restrict__ x, __half* __restrict__ xh, int n4)
{
    int i = blockIdx.x * 256 + threadIdx.x;
    if (i >= n4) return;
    float4 v = ((const float4*)x)[i];
    ((__half2*)xh)[i * 2]     = __floats2half2_rn(v.x, v.y);
    ((__half2*)xh)[i * 2 + 1] = __floats2half2_rn(v.z, v.w);
}

__global__ void transp(const float* __restrict__ s0, const float* __restrict__ s1,
                       __half* __restrict__ d0, __half* __restrict__ d1, int N)
{
    const float* src = blockIdx.z ? s1 : s0;
    __half*      dst = blockIdx.z ? d1 : d0;
    __shared__ float t[32][33];
    int n0 = blockIdx.x * 32, k0 = blockIdx.y * 32;
    int x = threadIdx.x, y = threadIdx.y;
#pragma unroll
    for (int j = 0; j < 32; j += 8)
        t[y + j][x] = src[(size_t)(k0 + y + j) * N + n0 + x];
    __syncthreads();
#pragma unroll
    for (int j = 0; j < 32; j += 8)
        dst[(size_t)(n0 + y + j) * D_ + k0 + x] = __float2half(t[x][y + j]);
}

// ---------------------------------------------------------------------------
// QKV GEMM: 128x64 CTA tiles, 4 warps (warp tile 32x64), cp.async 3-stage
// (46 KB smem/CTA -> 3 CTAs/SM resident). Per-batch grid (48, 8).
// ---------------------------------------------------------------------------
#define GP     40
#define A2_B   (128 * GP * 2)
#define ST2_B  (192 * GP * 2)      // 15360 B / stage
#define NSTGQ  3
#define NITER  (D_ / 32)

__global__ __launch_bounds__(128, 3) void gemm_qkv(
    const __half* __restrict__ A,
    const __half* __restrict__ W0, const __half* __restrict__ W1,
    const __half* __restrict__ W2,
    const float* __restrict__ cosb, const float* __restrict__ sinb,
    int mbase)
{
    extern __shared__ __half sh[];
    const int bx = blockIdx.x, by = blockIdx.y;
    const int tid = threadIdx.x, lane = tid & 31, wid = tid >> 5;
    const int g = lane >> 2, t = lane & 3;
    const int wm = wid * 32;

    const __half* Wt;
    int ctile, sel;
    if (bx < 32)      { Wt = W0; ctile = bx;      sel = 0; }
    else if (bx < 40) { Wt = W1; ctile = bx - 32; sel = 1; }
    else              { Wt = W2; ctile = bx - 40; sel = 2; }

    const __half* Ab = A  + (size_t)(mbase + by * 128) * D_;
    const __half* Bb = Wt + (size_t)ctile * 64 * D_;

    const uint32_t sbase = (uint32_t)__cvta_generic_to_shared(sh);

    auto issue = [&](int stage, int k0) {
        uint32_t sa = sbase + stage * ST2_B;
#pragma unroll
        for (int j = 0; j < 4; j++) {
            int idx = tid + j * 128;
            int r = idx >> 2, c = idx & 3;
            cp16(sa + (r * GP + c * 8) * 2, Ab + (size_t)r * D_ + k0 + c * 8);
        }
#pragma unroll
        for (int j = 0; j < 2; j++) {
            int idx = tid + j * 128;
            int r = idx >> 2, c = idx & 3;
            cp16(sa + A2_B + (r * GP + c * 8) * 2, Bb + (size_t)r * D_ + k0 + c * 8);
        }
    };

    uint32_t aoff[2], boff[4];
#pragma unroll
    for (int mt = 0; mt < 2; mt++)
        aoff[mt] = ((wm + mt * 16 + (lane & 7) + ((lane >> 3) & 1) * 8) * GP
                    + (lane >> 4) * 8) * 2;
#pragma unroll
    for (int p = 0; p < 4; p++)
        boff[p] = (uint32_t)A2_B +
                  ((p * 16 + (lane & 7) + ((lane >> 4) & 1) * 8) * GP
                   + ((lane >> 3) & 1) * 8) * 2;

    float acc[2][8][4] = {};

    issue(0, 0);  cp_commit();
    issue(1, 32); cp_commit();

    for (int it = 0; it < NITER; ++it) {
        cp_wait1();
        __syncthreads();
        if (it + 2 < NITER) issue((it + 2) % NSTGQ, (it + 2) * 32);
        cp_commit();

        const uint32_t sstg = sbase + (uint32_t)(it % NSTGQ) * ST2_B;
#pragma unroll
        for (int kk = 0; kk < 2; kk++) {
            const uint32_t kb = kk * 32;
            uint32_t af[2][4];
#pragma unroll
            for (int mt = 0; mt < 2; mt++)
                ldsm_x4(af[mt][0], af[mt][1], af[mt][2], af[mt][3],
                        sstg + aoff[mt] + kb);
            uint32_t bf[8][2];
#pragma unroll
            for (int p = 0; p < 4; p++)
                ldsm_x4(bf[2 * p][0], bf[2 * p][1], bf[2 * p + 1][0], bf[2 * p + 1][1],
                        sstg + boff[p] + kb);
#pragma unroll
            for (int mt = 0; mt < 2; mt++)
#pragma unroll
                for (int nt = 0; nt < 8; nt++)
                    mma_f16(acc[mt][nt], af[mt][0], af[mt][1], af[mt][2], af[mt][3],
                            bf[nt][0], bf[nt][1]);
        }
        __syncthreads();
    }

#pragma unroll
    for (int mt = 0; mt < 2; mt++) {
        const int r0g = mbase + by * 128 + wm + mt * 16 + g;
        const int r1g = r0g + 8;

        if (sel == 2) {
            int b0 = r0g >> 10, s0 = r0g & (S_ - 1);
            int b1 = r1g >> 10, s1 = r1g & (S_ - 1);
#pragma unroll
            for (int nt = 0; nt < 8; nt++) {
                int colk = ctile * 64 + nt * 8 + t * 2;
                int gh = colk >> 6, d = colk & 63;
                size_t base0 = ((size_t)(b0 * HKV_ + gh) * HD_) * S_;
                size_t base1 = ((size_t)(b1 * HKV_ + gh) * HD_) * S_;
                g_vt[base0 + (size_t)d * S_ + s0]       = __float2half(acc[mt][nt][0]);
                g_vt[base0 + (size_t)(d + 1) * S_ + s0] = __float2half(acc[mt][nt][1]);
                g_vt[base1 + (size_t)d * S_ + s1]       = __float2half(acc[mt][nt][2]);
                g_vt[base1 + (size_t)(d + 1) * S_ + s1] = __float2half(acc[mt][nt][3]);
            }
        } else {
            int s0 = r0g & (S_ - 1), s1 = r1g & (S_ - 1);
#pragma unroll
            for (int nt = 0; nt < 4; nt++) {
                int d = nt * 8 + 2 * t;
                float c0a = cosb[s0 * HD_ + d], c0b = cosb[s0 * HD_ + d + 1];
                float z0a = sinb[s0 * HD_ + d], z0b = sinb[s0 * HD_ + d + 1];
                float c1a = cosb[s1 * HD_ + d], c1b = cosb[s1 * HD_ + d + 1];
                float z1a = sinb[s1 * HD_ + d], z1b = sinb[s1 * HD_ + d + 1];
                float a, b;
                a = acc[mt][nt][0]; b = acc[mt][nt + 4][0];
                acc[mt][nt][0] = a * c0a - b * z0a;  acc[mt][nt + 4][0] = b * c0a + a * z0a;
                a = acc[mt][nt][1]; b = acc[mt][nt + 4][1];
                acc[mt][nt][1] = a * c0b - b * z0b;  acc[mt][nt + 4][1] = b * c0b + a * z0b;
                a = acc[mt][nt][2]; b = acc[mt][nt + 4][2];
                acc[mt][nt][2] = a * c1a - b * z1a;  acc[mt][nt + 4][2] = b * c1a + a * z1a;
                a = acc[mt][nt][3]; b = acc[mt][nt + 4][3];
                acc[mt][nt][3] = a * c1b - b * z1b;  acc[mt][nt + 4][3] = b * c1b + a * z1b;
            }
            __half* dst = (sel == 0) ? g_qh : g_kh;
            const int pitch = (sel == 0) ? NQ_ : NKV_;
            const int cb = ctile * 64;
#pragma unroll
            for (int nt = 0; nt < 8; nt++) {
                int col = cb + nt * 8 + t * 2;
                *(__half2*)&dst[(size_t)r0g * pitch + col] =
                    __floats2half2_rn(acc[mt][nt][0], acc[mt][nt][1]);
                *(__half2*)&dst[(size_t)r1g * pitch + col] =
                    __floats2half2_rn(acc[mt][nt][2], acc[mt][nt][3]);
            }
        }
    }
}

// ---------------------------------------------------------------------------
// O-projection GEMM: 128x128 CTA tiles, per-batch grid (16, 8), 4-stage.
// ---------------------------------------------------------------------------
#define ST_B  (2 * 128 * GP * 2)
#define AB_B  (128 * GP * 2)
#define NSTGO 4

__global__ __launch_bounds__(128, 2) void gemm_o(
    const __half* __restrict__ A,
    const __half* __restrict__ W0,
    float* __restrict__ Cf, int mbase)
{
    extern __shared__ __half sh[];
    const int bx = blockIdx.x, by = blockIdx.y;
    const int tid = threadIdx.x, lane = tid & 31, wid = tid >> 5;
    const int g = lane >> 2, t = lane & 3;
    const int wm = (wid & 1) * 64, wn = (wid >> 1) * 64;

    const __half* Ab = A  + (size_t)(mbase + by * 128) * D_;
    const __half* Bb = W0 + (size_t)bx * 128 * D_;

    const uint32_t sbase = (uint32_t)__cvta_generic_to_shared(sh);

    auto issue = [&](int stage, int k0) {
        uint32_t sa = sbase + stage * ST_B;
#pragma unroll
        for (int j = 0; j < 4; j++) {
            int idx = tid + j * 128;
            int r = idx >> 2, c = idx & 3;
            cp16(sa +        (r * GP + c * 8) * 2, Ab + (size_t)r * D_ + k0 + c * 8);
            cp16(sa + AB_B + (r * GP + c * 8) * 2, Bb + (size_t)r * D_ + k0 + c * 8);
        }
    };

    uint32_t aoff[4], boff[4];
#pragma unroll
    for (int mt = 0; mt < 4; mt++)
        aoff[mt] = ((wm + mt * 16 + (lane & 7) + ((lane >> 3) & 1) * 8) * GP
                    + (lane >> 4) * 8) * 2;
#pragma unroll
    for (int p = 0; p < 4; p++)
        boff[p] = (uint32_t)AB_B +
                  ((wn + p * 16 + (lane & 7) + ((lane >> 4) & 1) * 8) * GP
                   + ((lane >> 3) & 1) * 8) * 2;

    float acc[4][8][4] = {};

    issue(0, 0);  cp_commit();
    issue(1, 32); cp_commit();
    issue(2, 64); cp_commit();

    for (int it = 0; it < NITER; ++it) {
        cp_wait2();
        __syncthreads();
        if (it + 3 < NITER) issue((it + 3) & 3, (it + 3) * 32);
        cp_commit();

        const uint32_t sstg = sbase + (uint32_t)(it & 3) * ST_B;
#pragma unroll
        for (int kk = 0; kk < 2; kk++) {
            const uint32_t kb = kk * 32;
            uint32_t af[4][4];
#pragma unroll
            for (int mt = 0; mt < 4; mt++)
                ldsm_x4(af[mt][0], af[mt][1], af[mt][2], af[mt][3],
                        sstg + aoff[mt] + kb);
            uint32_t bf[8][2];
#pragma unroll
            for (int p = 0; p < 4; p++)
                ldsm_x4(bf[2 * p][0], bf[2 * p][1], bf[2 * p + 1][0], bf[2 * p + 1][1],
                        sstg + boff[p] + kb);
#pragma unroll
            for (int mt = 0; mt < 4; mt++)
#pragma unroll
                for (int nt = 0; nt < 8; nt++)
                    mma_f16(acc[mt][nt], af[mt][0], af[mt][1], af[mt][2], af[mt][3],
                            bf[nt][0], bf[nt][1]);
        }
    }

#pragma unroll
    for (int mt = 0; mt < 4; mt++) {
        const int r0g = mbase + by * 128 + wm + mt * 16 + g;
        const int r1g = r0g + 8;
#pragma unroll
        for (int nt = 0; nt < 8; nt++) {
            int col = bx * 128 + wn + nt * 8 + t * 2;
            *(float2*)&Cf[(size_t)r0g * NQ_ + col] =
                make_float2(acc[mt][nt][0], acc[mt][nt][1]);
            *(float2*)&Cf[(size_t)r1g * NQ_ + col] =
                make_float2(acc[mt][nt][2], acc[mt][nt][3]);
        }
    }
}

// ---------------------------------------------------------------------------
// Flash attention with balanced tile pairing (R12): grid (4, 32) per batch;
// CTA x does q-tiles {x, 7-x} -> every CTA 18 k-iterations.
// ---------------------------------------------------------------------------
#define FP_   72
#define FPW_  36
#define KVT_B (64 * FP_ * 2)
#define FQ_OFF 0
#define FK_OFF 18432
#define FV_OFF 36864
#define FPOFF  55296
#define FSMEM  73728

__global__ __launch_bounds__(256) void flash_h(
    const __half* __restrict__ Q,
    const __half* __restrict__ K,
    const __half* __restrict__ Vt,
    __half* __restrict__ Ctx, int b)
{
    extern __shared__ __half fsh[];
    const uint32_t sb  = (uint32_t)__cvta_generic_to_shared(fsh);
    const uint32_t qsb = sb + FQ_OFF;
    const uint32_t ksb = sb + FK_OFF;
    const uint32_t vsb = sb + FV_OFF;
    const uint32_t psb = sb + FPOFF;
    __half* Ps = fsh + FPOFF / 2;

    const int h   = blockIdx.y;
    const int gh  = h / REP_;
    const int tid = threadIdx.x;
    const int lane = tid & 31;
    const int wid  = tid >> 5;
    const int g    = lane >> 2;
    const int t    = lane & 3;
    const int r0   = wid * 16 + g;

    const uint32_t aoff = ((wid * 16 + (lane & 7) + ((lane >> 3) & 1) * 8) * FP_
                           + (lane >> 4) * 8) * 2;
    uint32_t boff[4];
#pragma unroll
    for (int p = 0; p < 4; p++)
        boff[p] = ((p * 16 + (lane & 7) + ((lane >> 4) & 1) * 8) * FP_
                   + ((lane >> 3) & 1) * 8) * 2;

    const __half* Kbase  = K  + ((size_t)(b * S_)) * NKV_ + gh * HD_;
    const __half* Vtbase = Vt + ((size_t)(b * HKV_ + gh)) * HD_ * S_;
    auto loadKV = [&](int st, int kt) {
        uint32_t kst = ksb + st * KVT_B;
        uint32_t vst = vsb + st * KVT_B;
        const __half* Kb  = Kbase  + (size_t)(kt * 64) * NKV_;
        const __half* Vtb = Vtbase + kt * 64;
#pragma unroll
        for (int j = 0; j < 2; j++) {
            int idx = tid + j * 256;
            int r = idx >> 3, c = idx & 7;
            cp16(kst + r * 144 + c * 16, Kb  + (size_t)r * NKV_ + c * 8);
            cp16(vst + r * 144 + c * 16, Vtb + (size_t)r * S_ + c * 8);
        }
    };

#pragma unroll 1
    for (int half = 0; half < 2; half++) {
        const int qt = (half == 0) ? (int)blockIdx.x : 7 - (int)blockIdx.x;
        const int ktmax = 2 * qt + 1;

        __syncthreads();

        const __half* Qb = Q + ((size_t)(b * S_ + qt * 128)) * NQ_ + h * HD_;
#pragma unroll
        for (int j = 0; j < 4; j++) {
            int idx = tid + j * 256;
            int r = idx >> 3, c = (idx & 7) * 8;
            *(uint4*)&fsh[(FQ_OFF / 2) + r * FP_ + c] =
                *(const uint4*)(Qb + (size_t)r * NQ_ + c);
        }

        float m0 = -INFINITY, m1 = -INFINITY, l0 = 0.f, l1 = 0.f;
        float oc[8][4] = {};

        loadKV(0, 0);
        cp_commit();

        for (int kt = 0; kt <= ktmax; kt++) {
            __syncthreads();
            int ktn = (kt + 1 <= ktmax) ? kt + 1 : ktmax;
            loadKV((kt + 1) & 1, ktn);
            cp_commit();
            cp_wait1();
            __syncthreads();

            const uint32_t kstg = ksb + (uint32_t)(kt & 1) * KVT_B;
            const uint32_t vstg = vsb + (uint32_t)(kt & 1) * KVT_B;

            float sc[8][4] = {};
#pragma unroll
            for (int kk = 0; kk < 4; kk++) {
                const uint32_t kb = kk * 32;
                uint32_t a0, a1, a2, a3;
                ldsm_x4(a0, a1, a2, a3, qsb + aoff + kb);
                uint32_t bf[8][2];
#pragma unroll
                for (int p = 0; p < 4; p++)
                    ldsm_x4(bf[2 * p][0], bf[2 * p][1], bf[2 * p + 1][0], bf[2 * p + 1][1],
                            kstg + boff[p] + kb);
#pragma unroll
                for (int nt = 0; nt < 8; nt++)
                    mma_f16(sc[nt], a0, a1, a2, a3, bf[nt][0], bf[nt][1]);
            }

            const bool diag = (kt * 64 + 63 > qt * 128 + wid * 16);
            const int gr0 = qt * 128 + r0;
            const int gc0 = kt * 64 + t * 2;
            float mn0 = m0, mn1 = m1;
#pragma unroll
            for (int nt = 0; nt < 8; nt++) {
#pragma unroll
                for (int j = 0; j < 4; j++) sc[nt][j] *= 0.125f;
                if (diag) {
                    int gc = gc0 + nt * 8;
                    if (gc     > gr0)     sc[nt][0] = -INFINITY;
                    if (gc + 1 > gr0)     sc[nt][1] = -INFINITY;
                    if (gc     > gr0 + 8) sc[nt][2] = -INFINITY;
                    if (gc + 1 > gr0 + 8) sc[nt][3] = -INFINITY;
                }
                mn0 = fmaxf(mn0, fmaxf(sc[nt][0], sc[nt][1]));
                mn1 = fmaxf(mn1, fmaxf(sc[nt][2], sc[nt][3]));
            }
            mn0 = fmaxf(mn0, __shfl_xor_sync(0xffffffffu, mn0, 1));
            mn0 = fmaxf(mn0, __shfl_xor_sync(0xffffffffu, mn0, 2));
            mn1 = fmaxf(mn1, __shfl_xor_sync(0xffffffffu, mn1, 1));
            mn1 = fmaxf(mn1, __shfl_xor_sync(0xffffffffu, mn1, 2));

            float al0 = __expf(m0 - mn0);
            float al1 = __expf(m1 - mn1);
            m0 = mn0; m1 = mn1;

            float rs0 = 0.f, rs1 = 0.f;
#pragma unroll
            for (int nt = 0; nt < 8; nt++) {
                sc[nt][0] = __expf(sc[nt][0] - mn0);
                sc[nt][1] = __expf(sc[nt][1] - mn0);
                sc[nt][2] = __expf(sc[nt][2] - mn1);
                sc[nt][3] = __expf(sc[nt][3] - mn1);
                rs0 += sc[nt][0] + sc[nt][1];
                rs1 += sc[nt][2] + sc[nt][3];
            }
            rs0 += __shfl_xor_sync(0xffffffffu, rs0, 1);
            rs0 += __shfl_xor_sync(0xffffffffu, rs0, 2);
            rs1 += __shfl_xor_sync(0xffffffffu, rs1, 1);
            rs1 += __shfl_xor_sync(0xffffffffu, rs1, 2);
            l0 = l0 * al0 + rs0;
            l1 = l1 * al1 + rs1;

#pragma unroll
            for (int dt = 0; dt < 8; dt++) {
                oc[dt][0] *= al0; oc[dt][1] *= al0;
                oc[dt][2] *= al1; oc[dt][3] *= al1;
            }

#pragma unroll
            for (int nt = 0; nt < 8; nt++) {
                ((__half2*)Ps)[r0 * FPW_ + nt * 4 + t]       = __floats2half2_rn(sc[nt][0], sc[nt][1]);
                ((__half2*)Ps)[(r0 + 8) * FPW_ + nt * 4 + t] = __floats2half2_rn(sc[nt][2], sc[nt][3]);
            }
            __syncwarp();

#pragma unroll
            for (int kk = 0; kk < 4; kk++) {
                const uint32_t kb = kk * 32;
                uint32_t a0, a1, a2, a3;
                ldsm_x4(a0, a1, a2, a3, psb + aoff + kb);
                uint32_t bf[8][2];
#pragma unroll
                for (int p = 0; p < 4; p++)
                    ldsm_x4(bf[2 * p][0], bf[2 * p][1], bf[2 * p + 1][0], bf[2 * p + 1][1],
                            vstg + boff[p] + kb);
#pragma unroll
                for (int dt = 0; dt < 8; dt++)
                    mma_f16(oc[dt], a0, a1, a2, a3, bf[dt][0], bf[dt][1]);
            }
        }
        cp_wait0();

        const float inv0 = 1.f / l0;
        const float inv1 = 1.f / l1;
        __half* Ob = Ctx + ((size_t)(b * S_ + qt * 128)) * NQ_ + h * HD_;
#pragma unroll
        for (int dt = 0; dt < 8; dt++) {
            int c = dt * 8 + t * 2;
            *(__half2*)&Ob[(size_t)r0 * NQ_ + c] =
                __floats2half2_rn(oc[dt][0] * inv0, oc[dt][1] * inv0);
            *(__half2*)&Ob[(size_t)(r0 + 8) * NQ_ + c] =
                __floats2half2_rn(oc[dt][2] * inv1, oc[dt][3] * inv1);
        }
    }
}

// ---------------------------------------------------------------------------
// Host launch: two batch chains + parallel prologue across persistent streams.
//   stream0: conv_x(b0) -> [eTwq,eTwkv] qkv(b0) -> flash(b0) -> [eWo] oproj(b0)
//   s1:      transp wq (eTwq) -> [eTwkv,eConv1] qkv(b1) -> flash(b1) -> [eWo] oproj(b1)
//   s2:      transp wk/wv (eTwkv) -> transp wo (eWo)
//   s3:      conv_x(b1) (eConv1)
// ---------------------------------------------------------------------------
extern "C" void kernel_launch(void* const* d_in, const int* in_sizes, int n_in,
                              void* d_out, int out_size)
{
    const float* x    = (const float*)d_in[0];
    const float* wq   = (const float*)d_in[1];
    const float* wk   = (const float*)d_in[2];
    const float* wv   = (const float*)d_in[3];
    const float* wo   = (const float*)d_in[4];
    const float* cosb = (const float*)d_in[5];
    const float* sinb = (const float*)d_in[6];
    float* out = (float*)d_out;

    __half *xh, *wqt, *wkt, *wvt, *wot, *qh, *kh, *vt, *ctxh;
    cudaGetSymbolAddress((void**)&xh,   g_xh);
    cudaGetSymbolAddress((void**)&wqt,  g_wqt);
    cudaGetSymbolAddress((void**)&wkt,  g_wkt);
    cudaGetSymbolAddress((void**)&wvt,  g_wvt);
    cudaGetSymbolAddress((void**)&wot,  g_wot);
    cudaGetSymbolAddress((void**)&qh,   g_qh);
    cudaGetSymbolAddress((void**)&kh,   g_kh);
    cudaGetSymbolAddress((void**)&vt,   g_vt);
    cudaGetSymbolAddress((void**)&ctxh, g_ctxh);

    const int smem_qkv = NSTGQ * ST2_B;   // 46080
    const int smem_o   = NSTGO * ST_B;    // 81920
    cudaFuncSetAttribute(gemm_qkv, cudaFuncAttributeMaxDynamicSharedMemorySize, smem_qkv);
    cudaFuncSetAttribute(gemm_o,   cudaFuncAttributeMaxDynamicSharedMemorySize, smem_o);
    cudaFuncSetAttribute(flash_h,  cudaFuncAttributeMaxDynamicSharedMemorySize, FSMEM);

    cudaStream_t s1 = g_sc.s1, s2 = g_sc.s2, s3 = g_sc.s3;
    const int HB4 = S_ * D_ / 4;

    // fork
    cudaEventRecord(g_sc.eFork, 0);
    cudaStreamWaitEvent(s1, g_sc.eFork, 0);
    cudaStreamWaitEvent(s2, g_sc.eFork, 0);
    cudaStreamWaitEvent(s3, g_sc.eFork, 0);

    // prologue (all concurrent)
    conv_x<<<(HB4 + 255) / 256, 256, 0, 0>>>(x, xh, HB4);                       // b0
    conv_x<<<(HB4 + 255) / 256, 256, 0, s3>>>(x + S_ * D_, xh + S_ * D_, HB4);  // b1
    cudaEventRecord(g_sc.eConv1, s3);

    transp<<<dim3(NQ_ / 32, D_ / 32, 1), dim3(32, 8), 0, s1>>>(wq, wq, wqt, wqt, NQ_);
    cudaEventRecord(g_sc.eTwq, s1);

    transp<<<dim3(NKV_ / 32, D_ / 32, 2), dim3(32, 8), 0, s2>>>(wk, wv, wkt, wvt, NKV_);
    cudaEventRecord(g_sc.eTwkv, s2);
    transp<<<dim3(NQ_ / 32, D_ / 32, 1), dim3(32, 8), 0, s2>>>(wo, wo, wot, wot, NQ_);
    cudaEventRecord(g_sc.eWo, s2);

    // chain b0 on default stream (conv b0 by stream order; needs wq + wk/wv)
    cudaStreamWaitEvent(0, g_sc.eTwq, 0);
    cudaStreamWaitEvent(0, g_sc.eTwkv, 0);
    gemm_qkv<<<dim3(48, 8), 128, smem_qkv, 0>>>(xh, wqt, wkt, wvt, cosb, sinb, 0);
    flash_h<<<dim3(4, 32), 256, FSMEM, 0>>>(qh, kh, vt, ctxh, 0);
    cudaStreamWaitEvent(0, g_sc.eWo, 0);
    gemm_o<<<dim3(16, 8), 128, smem_o, 0>>>(ctxh, wot, out, 0);

    // chain b1 on s1 (wq transp by stream order; needs wk/wv + conv b1)
    cudaStreamWaitEvent(s1, g_sc.eTwkv, 0);
    cudaStreamWaitEvent(s1, g_sc.eConv1, 0);
    gemm_qkv<<<dim3(48, 8), 128, smem_qkv, s1>>>(xh, wqt, wkt, wvt, cosb, sinb, S_);
    flash_h<<<dim3(4, 32), 256, FSMEM, s1>>>(qh, kh, vt, ctxh, 1);
    cudaStreamWaitEvent(s1, g_sc.eWo, 0);
    gemm_o<<<dim3(16, 8), 128, smem_o, s1>>>(ctxh, wot, out, S_);
    cudaEventRecord(g_sc.eC1, s1);

    // join
    cudaStreamWaitEvent(0, g_sc.eC1, 0);
}

// round 15
// speedup vs baseline: 1.0953x; 1.0126x over previous
#include <cuda_runtime.h>
#include <cuda_fp16.h>
#include <math.h>
#include <stdint.h>

#define B_    2
#define S_    1024
#define D_    2048
#define H_    32
#define HKV_  8
#define HD_   64
#define REP_  4
#define M_    (B_ * S_)       // 2048
#define NQ_   (H_ * HD_)      // 2048
#define NKV_  (HKV_ * HD_)    // 512

// ---------------------------------------------------------------------------
// Device-global scratch (no cudaMalloc allowed)
// ---------------------------------------------------------------------------
__device__ __half g_xh [M_ * D_];
__device__ __half g_wqt[NQ_ * D_];
__device__ __half g_wkt[NKV_ * D_];
__device__ __half g_wvt[NKV_ * D_];
__device__ __half g_wot[D_ * NQ_];
__device__ __half g_qh [M_ * NQ_];
__device__ __half g_kh [M_ * NKV_];
__device__ __half g_vt [B_ * HKV_ * HD_ * S_];   // [b][gh][d][s]
__device__ __half g_ctxh[M_ * NQ_];

// ---------------------------------------------------------------------------
// Persistent streams/events (created once pre-main; never in kernel_launch)
// ---------------------------------------------------------------------------
struct StreamCtx {
    cudaStream_t s1, s2, s3;
    cudaEvent_t  eFork, eTwq, eTwkv, eWo, eConv1, eC1;
    StreamCtx() {
        cudaStreamCreateWithFlags(&s1, cudaStreamNonBlocking);
        cudaStreamCreateWithFlags(&s2, cudaStreamNonBlocking);
        cudaStreamCreateWithFlags(&s3, cudaStreamNonBlocking);
        cudaEvent_t* evs[] = {&eFork, &eTwq, &eTwkv, &eWo, &eConv1, &eC1};
        for (auto e : evs) cudaEventCreateWithFlags(e, cudaEventDisableTiming);
    }
};
static StreamCtx g_sc;

// ---------------------------------------------------------------------------
// device helpers
// ---------------------------------------------------------------------------
__device__ __forceinline__ void mma_f16(float* c,
        uint32_t a0, uint32_t a1, uint32_t a2, uint32_t a3,
        uint32_t b0, uint32_t b1) {
    asm volatile(
        "mma.sync.aligned.m16n8k16.row.col.f32.f16.f16.f32 "
        "{%0,%1,%2,%3}, {%4,%5,%6,%7}, {%8,%9}, {%0,%1,%2,%3};"
        : "+f"(c[0]), "+f"(c[1]), "+f"(c[2]), "+f"(c[3])
        : "r"(a0), "r"(a1), "r"(a2), "r"(a3), "r"(b0), "r"(b1));
}

__device__ __forceinline__ void ldsm_x4(uint32_t& r0, uint32_t& r1,
                                        uint32_t& r2, uint32_t& r3, uint32_t addr) {
    asm volatile("ldmatrix.sync.aligned.m8n8.x4.shared.b16 {%0,%1,%2,%3}, [%4];"
                 : "=r"(r0), "=r"(r1), "=r"(r2), "=r"(r3) : "r"(addr));
}

__device__ __forceinline__ void cp16(uint32_t saddr, const void* gptr) {
    asm volatile("cp.async.cg.shared.global [%0], [%1], 16;"
                 :: "r"(saddr), "l"(gptr) : "memory");
}
__device__ __forceinline__ void cp_commit() {
    asm volatile("cp.async.commit_group;" ::: "memory");
}
__device__ __forceinline__ void cp_wait1() {
    asm volatile("cp.async.wait_group 1;" ::: "memory");
}
__device__ __forceinline__ void cp_wait0() {
    asm volatile("cp.async.wait_group 0;" ::: "memory");
}

__device__ __forceinline__ uint32_t packh2(float a, float b) {
    __half2 hv = __floats2half2_rn(a, b);
    return *reinterpret_cast<uint32_t*>(&hv);
}

// ---------------------------------------------------------------------------
// Converters
// ---------------------------------------------------------------------------
__global__ void conv_x(const float* __restrict__ x, __half* __restrict__ xh, int n4)
{
    int i = blockIdx.x * 256 + threadIdx.x;
    if (i >= n4) return;
    float4 v = ((const float4*)x)[i];
    ((__half2*)xh)[i * 2]     = __floats2half2_rn(v.x, v.y);
    ((__half2*)xh)[i * 2 + 1] = __floats2half2_rn(v.z, v.w);
}

__global__ void transp(const float* __restrict__ s0, const float* __restrict__ s1,
                       __half* __restrict__ d0, __half* __restrict__ d1, int N)
{
    const float* src = blockIdx.z ? s1 : s0;
    __half*      dst = blockIdx.z ? d1 : d0;
    __shared__ float t[32][33];
    int n0 = blockIdx.x * 32, k0 = blockIdx.y * 32;
    int x = threadIdx.x, y = threadIdx.y;
#pragma unroll
    for (int j = 0; j < 32; j += 8)
        t[y + j][x] = src[(size_t)(k0 + y + j) * N + n0 + x];
    __syncthreads();
#pragma unroll
    for (int j = 0; j < 32; j += 8)
        dst[(size_t)(n0 + y + j) * D_ + k0 + x] = __float2half(t[x][y + j]);
}

// ---------------------------------------------------------------------------
// Shared GEMM config: 128x64 CTA tile, 4 warps (32x64 warp tile), 3 stages.
// ---------------------------------------------------------------------------
#define GP     40
#define A2_B   (128 * GP * 2)
#define ST2_B  (192 * GP * 2)      // 15360 B / stage
#define NSTGQ  3
#define NITER  (D_ / 32)

// ---------------------------------------------------------------------------
// QKV GEMM (rope/V-transpose epilogue). Per-batch grid (48, 8).
// ---------------------------------------------------------------------------
__global__ __launch_bounds__(128, 3) void gemm_qkv(
    const __half* __restrict__ A,
    const __half* __restrict__ W0, const __half* __restrict__ W1,
    const __half* __restrict__ W2,
    const float* __restrict__ cosb, const float* __restrict__ sinb,
    int mbase)
{
    extern __shared__ __half sh[];
    const int bx = blockIdx.x, by = blockIdx.y;
    const int tid = threadIdx.x, lane = tid & 31, wid = tid >> 5;
    const int g = lane >> 2, t = lane & 3;
    const int wm = wid * 32;

    const __half* Wt;
    int ctile, sel;
    if (bx < 32)      { Wt = W0; ctile = bx;      sel = 0; }
    else if (bx < 40) { Wt = W1; ctile = bx - 32; sel = 1; }
    else              { Wt = W2; ctile = bx - 40; sel = 2; }

    const __half* Ab = A  + (size_t)(mbase + by * 128) * D_;
    const __half* Bb = Wt + (size_t)ctile * 64 * D_;

    const uint32_t sbase = (uint32_t)__cvta_generic_to_shared(sh);

    auto issue = [&](int stage, int k0) {
        uint32_t sa = sbase + stage * ST2_B;
#pragma unroll
        for (int j = 0; j < 4; j++) {
            int idx = tid + j * 128;
            int r = idx >> 2, c = idx & 3;
            cp16(sa + (r * GP + c * 8) * 2, Ab + (size_t)r * D_ + k0 + c * 8);
        }
#pragma unroll
        for (int j = 0; j < 2; j++) {
            int idx = tid + j * 128;
            int r = idx >> 2, c = idx & 3;
            cp16(sa + A2_B + (r * GP + c * 8) * 2, Bb + (size_t)r * D_ + k0 + c * 8);
        }
    };

    uint32_t aoff[2], boff[4];
#pragma unroll
    for (int mt = 0; mt < 2; mt++)
        aoff[mt] = ((wm + mt * 16 + (lane & 7) + ((lane >> 3) & 1) * 8) * GP
                    + (lane >> 4) * 8) * 2;
#pragma unroll
    for (int p = 0; p < 4; p++)
        boff[p] = (uint32_t)A2_B +
                  ((p * 16 + (lane & 7) + ((lane >> 4) & 1) * 8) * GP
                   + ((lane >> 3) & 1) * 8) * 2;

    float acc[2][8][4] = {};

    issue(0, 0);  cp_commit();
    issue(1, 32); cp_commit();

    for (int it = 0; it < NITER; ++it) {
        cp_wait1();
        __syncthreads();
        if (it + 2 < NITER) issue((it + 2) % NSTGQ, (it + 2) * 32);
        cp_commit();

        const uint32_t sstg = sbase + (uint32_t)(it % NSTGQ) * ST2_B;
#pragma unroll
        for (int kk = 0; kk < 2; kk++) {
            const uint32_t kb = kk * 32;
            uint32_t af[2][4];
#pragma unroll
            for (int mt = 0; mt < 2; mt++)
                ldsm_x4(af[mt][0], af[mt][1], af[mt][2], af[mt][3],
                        sstg + aoff[mt] + kb);
            uint32_t bf[8][2];
#pragma unroll
            for (int p = 0; p < 4; p++)
                ldsm_x4(bf[2 * p][0], bf[2 * p][1], bf[2 * p + 1][0], bf[2 * p + 1][1],
                        sstg + boff[p] + kb);
#pragma unroll
            for (int mt = 0; mt < 2; mt++)
#pragma unroll
                for (int nt = 0; nt < 8; nt++)
                    mma_f16(acc[mt][nt], af[mt][0], af[mt][1], af[mt][2], af[mt][3],
                            bf[nt][0], bf[nt][1]);
        }
        __syncthreads();
    }

#pragma unroll
    for (int mt = 0; mt < 2; mt++) {
        const int r0g = mbase + by * 128 + wm + mt * 16 + g;
        const int r1g = r0g + 8;

        if (sel == 2) {
            int b0 = r0g >> 10, s0 = r0g & (S_ - 1);
            int b1 = r1g >> 10, s1 = r1g & (S_ - 1);
#pragma unroll
            for (int nt = 0; nt < 8; nt++) {
                int colk = ctile * 64 + nt * 8 + t * 2;
                int gh = colk >> 6, d = colk & 63;
                size_t base0 = ((size_t)(b0 * HKV_ + gh) * HD_) * S_;
                size_t base1 = ((size_t)(b1 * HKV_ + gh) * HD_) * S_;
                g_vt[base0 + (size_t)d * S_ + s0]       = __float2half(acc[mt][nt][0]);
                g_vt[base0 + (size_t)(d + 1) * S_ + s0] = __float2half(acc[mt][nt][1]);
                g_vt[base1 + (size_t)d * S_ + s1]       = __float2half(acc[mt][nt][2]);
                g_vt[base1 + (size_t)(d + 1) * S_ + s1] = __float2half(acc[mt][nt][3]);
            }
        } else {
            int s0 = r0g & (S_ - 1), s1 = r1g & (S_ - 1);
#pragma unroll
            for (int nt = 0; nt < 4; nt++) {
                int d = nt * 8 + 2 * t;
                float c0a = cosb[s0 * HD_ + d], c0b = cosb[s0 * HD_ + d + 1];
                float z0a = sinb[s0 * HD_ + d], z0b = sinb[s0 * HD_ + d + 1];
                float c1a = cosb[s1 * HD_ + d], c1b = cosb[s1 * HD_ + d + 1];
                float z1a = sinb[s1 * HD_ + d], z1b = sinb[s1 * HD_ + d + 1];
                float a, b;
                a = acc[mt][nt][0]; b = acc[mt][nt + 4][0];
                acc[mt][nt][0] = a * c0a - b * z0a;  acc[mt][nt + 4][0] = b * c0a + a * z0a;
                a = acc[mt][nt][1]; b = acc[mt][nt + 4][1];
                acc[mt][nt][1] = a * c0b - b * z0b;  acc[mt][nt + 4][1] = b * c0b + a * z0b;
                a = acc[mt][nt][2]; b = acc[mt][nt + 4][2];
                acc[mt][nt][2] = a * c1a - b * z1a;  acc[mt][nt + 4][2] = b * c1a + a * z1a;
                a = acc[mt][nt][3]; b = acc[mt][nt + 4][3];
                acc[mt][nt][3] = a * c1b - b * z1b;  acc[mt][nt + 4][3] = b * c1b + a * z1b;
            }
            __half* dst = (sel == 0) ? g_qh : g_kh;
            const int pitch = (sel == 0) ? NQ_ : NKV_;
            const int cb = ctile * 64;
#pragma unroll
            for (int nt = 0; nt < 8; nt++) {
                int col = cb + nt * 8 + t * 2;
                *(__half2*)&dst[(size_t)r0g * pitch + col] =
                    __floats2half2_rn(acc[mt][nt][0], acc[mt][nt][1]);
                *(__half2*)&dst[(size_t)r1g * pitch + col] =
                    __floats2half2_rn(acc[mt][nt][2], acc[mt][nt][3]);
            }
        }
    }
}

// ---------------------------------------------------------------------------
// O-projection GEMM: 128x64 tiles, 3 stages, 3 CTAs/SM. Per-batch (32, 8).
// ---------------------------------------------------------------------------
__global__ __launch_bounds__(128, 3) void gemm_o(
    const __half* __restrict__ A,
    const __half* __restrict__ W0,
    float* __restrict__ Cf, int mbase)
{
    extern __shared__ __half sh[];
    const int bx = blockIdx.x, by = blockIdx.y;
    const int tid = threadIdx.x, lane = tid & 31, wid = tid >> 5;
    const int g = lane >> 2, t = lane & 3;
    const int wm = wid * 32;

    const __half* Ab = A  + (size_t)(mbase + by * 128) * D_;
    const __half* Bb = W0 + (size_t)bx * 64 * D_;

    const uint32_t sbase = (uint32_t)__cvta_generic_to_shared(sh);

    auto issue = [&](int stage, int k0) {
        uint32_t sa = sbase + stage * ST2_B;
#pragma unroll
        for (int j = 0; j < 4; j++) {
            int idx = tid + j * 128;
            int r = idx >> 2, c = idx & 3;
            cp16(sa + (r * GP + c * 8) * 2, Ab + (size_t)r * D_ + k0 + c * 8);
        }
#pragma unroll
        for (int j = 0; j < 2; j++) {
            int idx = tid + j * 128;
            int r = idx >> 2, c = idx & 3;
            cp16(sa + A2_B + (r * GP + c * 8) * 2, Bb + (size_t)r * D_ + k0 + c * 8);
        }
    };

    uint32_t aoff[2], boff[4];
#pragma unroll
    for (int mt = 0; mt < 2; mt++)
        aoff[mt] = ((wm + mt * 16 + (lane & 7) + ((lane >> 3) & 1) * 8) * GP
                    + (lane >> 4) * 8) * 2;
#pragma unroll
    for (int p = 0; p < 4; p++)
        boff[p] = (uint32_t)A2_B +
                  ((p * 16 + (lane & 7) + ((lane >> 4) & 1) * 8) * GP
                   + ((lane >> 3) & 1) * 8) * 2;

    float acc[2][8][4] = {};

    issue(0, 0);  cp_commit();
    issue(1, 32); cp_commit();

    for (int it = 0; it < NITER; ++it) {
        cp_wait1();
        __syncthreads();
        if (it + 2 < NITER) issue((it + 2) % NSTGQ, (it + 2) * 32);
        cp_commit();

        const uint32_t sstg = sbase + (uint32_t)(it % NSTGQ) * ST2_B;
#pragma unroll
        for (int kk = 0; kk < 2; kk++) {
            const uint32_t kb = kk * 32;
            uint32_t af[2][4];
#pragma unroll
            for (int mt = 0; mt < 2; mt++)
                ldsm_x4(af[mt][0], af[mt][1], af[mt][2], af[mt][3],
                        sstg + aoff[mt] + kb);
            uint32_t bf[8][2];
#pragma unroll
            for (int p = 0; p < 4; p++)
                ldsm_x4(bf[2 * p][0], bf[2 * p][1], bf[2 * p + 1][0], bf[2 * p + 1][1],
                        sstg + boff[p] + kb);
#pragma unroll
            for (int mt = 0; mt < 2; mt++)
#pragma unroll
                for (int nt = 0; nt < 8; nt++)
                    mma_f16(acc[mt][nt], af[mt][0], af[mt][1], af[mt][2], af[mt][3],
                            bf[nt][0], bf[nt][1]);
        }
        __syncthreads();
    }

#pragma unroll
    for (int mt = 0; mt < 2; mt++) {
        const int r0g = mbase + by * 128 + wm + mt * 16 + g;
        const int r1g = r0g + 8;
#pragma unroll
        for (int nt = 0; nt < 8; nt++) {
            int col = bx * 64 + nt * 8 + t * 2;
            *(float2*)&Cf[(size_t)r0g * NQ_ + col] =
                make_float2(acc[mt][nt][0], acc[mt][nt][1]);
            *(float2*)&Cf[(size_t)r1g * NQ_ + col] =
                make_float2(acc[mt][nt][2], acc[mt][nt][3]);
        }
    }
}

// ---------------------------------------------------------------------------
// Flash attention: balanced tile pairing + REGISTER-DIRECT P (no smem stage).
// grid (4, 32) per batch; CTA x does q-tiles {x, 7-x}.
// ---------------------------------------------------------------------------
#define FP_   72
#define KVT_B (64 * FP_ * 2)
#define FQ_OFF 0
#define FK_OFF 18432
#define FV_OFF 36864
#define FSMEM  55296

__global__ __launch_bounds__(256) void flash_h(
    const __half* __restrict__ Q,
    const __half* __restrict__ K,
    const __half* __restrict__ Vt,
    __half* __restrict__ Ctx, int b)
{
    extern __shared__ __half fsh[];
    const uint32_t sb  = (uint32_t)__cvta_generic_to_shared(fsh);
    const uint32_t qsb = sb + FQ_OFF;
    const uint32_t ksb = sb + FK_OFF;
    const uint32_t vsb = sb + FV_OFF;

    const int h   = blockIdx.y;
    const int gh  = h / REP_;
    const int tid = threadIdx.x;
    const int lane = tid & 31;
    const int wid  = tid >> 5;
    const int g    = lane >> 2;
    const int t    = lane & 3;
    const int r0   = wid * 16 + g;

    const uint32_t aoff = ((wid * 16 + (lane & 7) + ((lane >> 3) & 1) * 8) * FP_
                           + (lane >> 4) * 8) * 2;
    uint32_t boff[4];
#pragma unroll
    for (int p = 0; p < 4; p++)
        boff[p] = ((p * 16 + (lane & 7) + ((lane >> 4) & 1) * 8) * FP_
                   + ((lane >> 3) & 1) * 8) * 2;

    const __half* Kbase  = K  + ((size_t)(b * S_)) * NKV_ + gh * HD_;
    const __half* Vtbase = Vt + ((size_t)(b * HKV_ + gh)) * HD_ * S_;
    auto loadKV = [&](int st, int kt) {
        uint32_t kst = ksb + st * KVT_B;
        uint32_t vst = vsb + st * KVT_B;
        const __half* Kb  = Kbase  + (size_t)(kt * 64) * NKV_;
        const __half* Vtb = Vtbase + kt * 64;
#pragma unroll
        for (int j = 0; j < 2; j++) {
            int idx = tid + j * 256;
            int r = idx >> 3, c = idx & 7;
            cp16(kst + r * 144 + c * 16, Kb  + (size_t)r * NKV_ + c * 8);
            cp16(vst + r * 144 + c * 16, Vtb + (size_t)r * S_ + c * 8);
        }
    };

#pragma unroll 1
    for (int half = 0; half < 2; half++) {
        const int qt = (half == 0) ? (int)blockIdx.x : 7 - (int)blockIdx.x;
        const int ktmax = 2 * qt + 1;

        __syncthreads();

        const __half* Qb = Q + ((size_t)(b * S_ + qt * 128)) * NQ_ + h * HD_;
#pragma unroll
        for (int j = 0; j < 4; j++) {
            int idx = tid + j * 256;
            int r = idx >> 3, c = (idx & 7) * 8;
            *(uint4*)&fsh[(FQ_OFF / 2) + r * FP_ + c] =
                *(const uint4*)(Qb + (size_t)r * NQ_ + c);
        }

        float m0 = -INFINITY, m1 = -INFINITY, l0 = 0.f, l1 = 0.f;
        float oc[8][4] = {};

        loadKV(0, 0);
        cp_commit();

        for (int kt = 0; kt <= ktmax; kt++) {
            __syncthreads();
            int ktn = (kt + 1 <= ktmax) ? kt + 1 : ktmax;
            loadKV((kt + 1) & 1, ktn);
            cp_commit();
            cp_wait1();
            __syncthreads();

            const uint32_t kstg = ksb + (uint32_t)(kt & 1) * KVT_B;
            const uint32_t vstg = vsb + (uint32_t)(kt & 1) * KVT_B;

            // S = Q K^T
            float sc[8][4] = {};
#pragma unroll
            for (int kk = 0; kk < 4; kk++) {
                const uint32_t kb = kk * 32;
                uint32_t a0, a1, a2, a3;
                ldsm_x4(a0, a1, a2, a3, qsb + aoff + kb);
                uint32_t bf[8][2];
#pragma unroll
                for (int p = 0; p < 4; p++)
                    ldsm_x4(bf[2 * p][0], bf[2 * p][1], bf[2 * p + 1][0], bf[2 * p + 1][1],
                            kstg + boff[p] + kb);
#pragma unroll
                for (int nt = 0; nt < 8; nt++)
                    mma_f16(sc[nt], a0, a1, a2, a3, bf[nt][0], bf[nt][1]);
            }

            const bool diag = (kt * 64 + 63 > qt * 128 + wid * 16);
            const int gr0 = qt * 128 + r0;
            const int gc0 = kt * 64 + t * 2;
            float mn0 = m0, mn1 = m1;
#pragma unroll
            for (int nt = 0; nt < 8; nt++) {
#pragma unroll
                for (int j = 0; j < 4; j++) sc[nt][j] *= 0.125f;
                if (diag) {
                    int gc = gc0 + nt * 8;
                    if (gc     > gr0)     sc[nt][0] = -INFINITY;
                    if (gc + 1 > gr0)     sc[nt][1] = -INFINITY;
                    if (gc     > gr0 + 8) sc[nt][2] = -INFINITY;
                    if (gc + 1 > gr0 + 8) sc[nt][3] = -INFINITY;
                }
                mn0 = fmaxf(mn0, fmaxf(sc[nt][0], sc[nt][1]));
                mn1 = fmaxf(mn1, fmaxf(sc[nt][2], sc[nt][3]));
            }
            mn0 = fmaxf(mn0, __shfl_xor_sync(0xffffffffu, mn0, 1));
            mn0 = fmaxf(mn0, __shfl_xor_sync(0xffffffffu, mn0, 2));
            mn1 = fmaxf(mn1, __shfl_xor_sync(0xffffffffu, mn1, 1));
            mn1 = fmaxf(mn1, __shfl_xor_sync(0xffffffffu, mn1, 2));

            float al0 = __expf(m0 - mn0);
            float al1 = __expf(m1 - mn1);
            m0 = mn0; m1 = mn1;

            float rs0 = 0.f, rs1 = 0.f;
            uint32_t p01[8], p23[8];     // P fragments, register-direct
#pragma unroll
            for (int nt = 0; nt < 8; nt++) {
                sc[nt][0] = __expf(sc[nt][0] - mn0);
                sc[nt][1] = __expf(sc[nt][1] - mn0);
                sc[nt][2] = __expf(sc[nt][2] - mn1);
                sc[nt][3] = __expf(sc[nt][3] - mn1);
                rs0 += sc[nt][0] + sc[nt][1];
                rs1 += sc[nt][2] + sc[nt][3];
                p01[nt] = packh2(sc[nt][0], sc[nt][1]);
                p23[nt] = packh2(sc[nt][2], sc[nt][3]);
            }
            rs0 += __shfl_xor_sync(0xffffffffu, rs0, 1);
            rs0 += __shfl_xor_sync(0xffffffffu, rs0, 2);
            rs1 += __shfl_xor_sync(0xffffffffu, rs1, 1);
            rs1 += __shfl_xor_sync(0xffffffffu, rs1, 2);
            l0 = l0 * al0 + rs0;
            l1 = l1 * al1 + rs1;

#pragma unroll
            for (int dt = 0; dt < 8; dt++) {
                oc[dt][0] *= al0; oc[dt][1] *= al0;
                oc[dt][2] *= al1; oc[dt][3] *= al1;
            }

            // O += P @ V  — A-fragments taken straight from the S C-fragments
#pragma unroll
            for (int p = 0; p < 4; p++) {
                const uint32_t kb = p * 32;
                uint32_t a0 = p01[2 * p];
                uint32_t a1 = p23[2 * p];
                uint32_t a2 = p01[2 * p + 1];
                uint32_t a3 = p23[2 * p + 1];
                uint32_t bf[8][2];
#pragma unroll
                for (int q = 0; q < 4; q++)
                    ldsm_x4(bf[2 * q][0], bf[2 * q][1], bf[2 * q + 1][0], bf[2 * q + 1][1],
                            vstg + boff[q] + kb);
#pragma unroll
                for (int dt = 0; dt < 8; dt++)
                    mma_f16(oc[dt], a0, a1, a2, a3, bf[dt][0], bf[dt][1]);
            }
        }
        cp_wait0();

        const float inv0 = 1.f / l0;
        const float inv1 = 1.f / l1;
        __half* Ob = Ctx + ((size_t)(b * S_ + qt * 128)) * NQ_ + h * HD_;
#pragma unroll
        for (int dt = 0; dt < 8; dt++) {
            int c = dt * 8 + t * 2;
            *(__half2*)&Ob[(size_t)r0 * NQ_ + c] =
                __floats2half2_rn(oc[dt][0] * inv0, oc[dt][1] * inv0);
            *(__half2*)&Ob[(size_t)(r0 + 8) * NQ_ + c] =
                __floats2half2_rn(oc[dt][2] * inv1, oc[dt][3] * inv1);
        }
    }
}

// ---------------------------------------------------------------------------
// Host launch: two batch chains + parallel prologue (persistent streams).
// ---------------------------------------------------------------------------
extern "C" void kernel_launch(void* const* d_in, const int* in_sizes, int n_in,
                              void* d_out, int out_size)
{
    const float* x    = (const float*)d_in[0];
    const float* wq   = (const float*)d_in[1];
    const float* wk   = (const float*)d_in[2];
    const float* wv   = (const float*)d_in[3];
    const float* wo   = (const float*)d_in[4];
    const float* cosb = (const float*)d_in[5];
    const float* sinb = (const float*)d_in[6];
    float* out = (float*)d_out;

    __half *xh, *wqt, *wkt, *wvt, *wot, *qh, *kh, *vt, *ctxh;
    cudaGetSymbolAddress((void**)&xh,   g_xh);
    cudaGetSymbolAddress((void**)&wqt,  g_wqt);
    cudaGetSymbolAddress((void**)&wkt,  g_wkt);
    cudaGetSymbolAddress((void**)&wvt,  g_wvt);
    cudaGetSymbolAddress((void**)&wot,  g_wot);
    cudaGetSymbolAddress((void**)&qh,   g_qh);
    cudaGetSymbolAddress((void**)&kh,   g_kh);
    cudaGetSymbolAddress((void**)&vt,   g_vt);
    cudaGetSymbolAddress((void**)&ctxh, g_ctxh);

    const int smem_g = NSTGQ * ST2_B;   // 46080
    cudaFuncSetAttribute(gemm_qkv, cudaFuncAttributeMaxDynamicSharedMemorySize, smem_g);
    cudaFuncSetAttribute(gemm_o,   cudaFuncAttributeMaxDynamicSharedMemorySize, smem_g);
    cudaFuncSetAttribute(flash_h,  cudaFuncAttributeMaxDynamicSharedMemorySize, FSMEM);

    cudaStream_t s1 = g_sc.s1, s2 = g_sc.s2, s3 = g_sc.s3;
    const int HB4 = S_ * D_ / 4;

    // fork
    cudaEventRecord(g_sc.eFork, 0);
    cudaStreamWaitEvent(s1, g_sc.eFork, 0);
    cudaStreamWaitEvent(s2, g_sc.eFork, 0);
    cudaStreamWaitEvent(s3, g_sc.eFork, 0);

    // prologue (concurrent)
    conv_x<<<(HB4 + 255) / 256, 256, 0, 0>>>(x, xh, HB4);                       // b0
    conv_x<<<(HB4 + 255) / 256, 256, 0, s3>>>(x + S_ * D_, xh + S_ * D_, HB4);  // b1
    cudaEventRecord(g_sc.eConv1, s3);

    transp<<<dim3(NQ_ / 32, D_ / 32, 1), dim3(32, 8), 0, s1>>>(wq, wq, wqt, wqt, NQ_);
    cudaEventRecord(g_sc.eTwq, s1);

    transp<<<dim3(NKV_ / 32, D_ / 32, 2), dim3(32, 8), 0, s2>>>(wk, wv, wkt, wvt, NKV_);
    cudaEventRecord(g_sc.eTwkv, s2);
    transp<<<dim3(NQ_ / 32, D_ / 32, 1), dim3(32, 8), 0, s2>>>(wo, wo, wot, wot, NQ_);
    cudaEventRecord(g_sc.eWo, s2);

    // chain b0 on default stream
    cudaStreamWaitEvent(0, g_sc.eTwq, 0);
    cudaStreamWaitEvent(0, g_sc.eTwkv, 0);
    gemm_qkv<<<dim3(48, 8), 128, smem_g, 0>>>(xh, wqt, wkt, wvt, cosb, sinb, 0);
    flash_h<<<dim3(4, 32), 256, FSMEM, 0>>>(qh, kh, vt, ctxh, 0);
    cudaStreamWaitEvent(0, g_sc.eWo, 0);
    gemm_o<<<dim3(32, 8), 128, smem_g, 0>>>(ctxh, wot, out, 0);

    // chain b1 on s1
    cudaStreamWaitEvent(s1, g_sc.eTwkv, 0);
    cudaStreamWaitEvent(s1, g_sc.eConv1, 0);
    gemm_qkv<<<dim3(48, 8), 128, smem_g, s1>>>(xh, wqt, wkt, wvt, cosb, sinb, S_);
    flash_h<<<dim3(4, 32), 256, FSMEM, s1>>>(qh, kh, vt, ctxh, 1);
    cudaStreamWaitEvent(s1, g_sc.eWo, 0);
    gemm_o<<<dim3(32, 8), 128, smem_g, s1>>>(ctxh, wot, out, S_);
    cudaEventRecord(g_sc.eC1, s1);

    // join
    cudaStreamWaitEvent(0, g_sc.eC1, 0);
}

// round 16
// speedup vs baseline: 1.1125x; 1.0157x over previous
#include <cuda_runtime.h>
#include <cuda_fp16.h>
#include <math.h>
#include <stdint.h>

#define B_    2
#define S_    1024
#define D_    2048
#define H_    32
#define HKV_  8
#define HD_   64
#define REP_  4
#define M_    (B_ * S_)       // 2048
#define NQ_   (H_ * HD_)      // 2048
#define NKV_  (HKV_ * HD_)    // 512

// ---------------------------------------------------------------------------
// Device-global scratch (no cudaMalloc allowed)
// ---------------------------------------------------------------------------
__device__ __half g_xh [M_ * D_];
__device__ __half g_wqt[NQ_ * D_];
__device__ __half g_wkt[NKV_ * D_];
__device__ __half g_wvt[NKV_ * D_];
__device__ __half g_wot[D_ * NQ_];
__device__ __half g_qh [M_ * NQ_];
__device__ __half g_kh [M_ * NKV_];
__device__ __half g_vt [B_ * HKV_ * HD_ * S_];   // [b][gh][d][s]
__device__ __half g_ctxh[M_ * NQ_];

// ---------------------------------------------------------------------------
// Persistent streams/events (created once pre-main; never in kernel_launch)
// ---------------------------------------------------------------------------
struct StreamCtx {
    cudaStream_t s1, s2, s3;
    cudaEvent_t  eFork, eTwq, eTwkv, eWo, eConv1, eC1;
    StreamCtx() {
        cudaStreamCreateWithFlags(&s1, cudaStreamNonBlocking);
        cudaStreamCreateWithFlags(&s2, cudaStreamNonBlocking);
        cudaStreamCreateWithFlags(&s3, cudaStreamNonBlocking);
        cudaEvent_t* evs[] = {&eFork, &eTwq, &eTwkv, &eWo, &eConv1, &eC1};
        for (auto e : evs) cudaEventCreateWithFlags(e, cudaEventDisableTiming);
    }
};
static StreamCtx g_sc;

// ---------------------------------------------------------------------------
// device helpers
// ---------------------------------------------------------------------------
__device__ __forceinline__ void mma_f16(float* c,
        uint32_t a0, uint32_t a1, uint32_t a2, uint32_t a3,
        uint32_t b0, uint32_t b1) {
    asm volatile(
        "mma.sync.aligned.m16n8k16.row.col.f32.f16.f16.f32 "
        "{%0,%1,%2,%3}, {%4,%5,%6,%7}, {%8,%9}, {%0,%1,%2,%3};"
        : "+f"(c[0]), "+f"(c[1]), "+f"(c[2]), "+f"(c[3])
        : "r"(a0), "r"(a1), "r"(a2), "r"(a3), "r"(b0), "r"(b1));
}

__device__ __forceinline__ void ldsm_x4(uint32_t& r0, uint32_t& r1,
                                        uint32_t& r2, uint32_t& r3, uint32_t addr) {
    asm volatile("ldmatrix.sync.aligned.m8n8.x4.shared.b16 {%0,%1,%2,%3}, [%4];"
                 : "=r"(r0), "=r"(r1), "=r"(r2), "=r"(r3) : "r"(addr));
}

__device__ __forceinline__ void cp16(uint32_t saddr, const void* gptr) {
    asm volatile("cp.async.cg.shared.global [%0], [%1], 16;"
                 :: "r"(saddr), "l"(gptr) : "memory");
}
__device__ __forceinline__ void cp_commit() {
    asm volatile("cp.async.commit_group;" ::: "memory");
}
__device__ __forceinline__ void cp_wait1() {
    asm volatile("cp.async.wait_group 1;" ::: "memory");
}
__device__ __forceinline__ void cp_wait0() {
    asm volatile("cp.async.wait_group 0;" ::: "memory");
}

__device__ __forceinline__ uint32_t packh2(float a, float b) {
    __half2 hv = __floats2half2_rn(a, b);
    return *reinterpret_cast<uint32_t*>(&hv);
}

// ---------------------------------------------------------------------------
// Converters
// ---------------------------------------------------------------------------
__global__ void conv_x(const float* __restrict__ x, __half* __restrict__ xh, int n4)
{
    int i = blockIdx.x * 256 + threadIdx.x;
    if (i >= n4) return;
    float4 v = ((const float4*)x)[i];
    ((__half2*)xh)[i * 2]     = __floats2half2_rn(v.x, v.y);
    ((__half2*)xh)[i * 2 + 1] = __floats2half2_rn(v.z, v.w);
}

__global__ void transp(const float* __restrict__ s0, const float* __restrict__ s1,
                       __half* __restrict__ d0, __half* __restrict__ d1, int N)
{
    const float* src = blockIdx.z ? s1 : s0;
    __half*      dst = blockIdx.z ? d1 : d0;
    __shared__ float t[32][33];
    int n0 = blockIdx.x * 32, k0 = blockIdx.y * 32;
    int x = threadIdx.x, y = threadIdx.y;
#pragma unroll
    for (int j = 0; j < 32; j += 8)
        t[y + j][x] = src[(size_t)(k0 + y + j) * N + n0 + x];
    __syncthreads();
#pragma unroll
    for (int j = 0; j < 32; j += 8)
        dst[(size_t)(n0 + y + j) * D_ + k0 + x] = __float2half(t[x][y + j]);
}

// ---------------------------------------------------------------------------
// Shared GEMM config: 128x64 CTA tile, 4 warps (32x64 warp tile), 3 stages.
// ---------------------------------------------------------------------------
#define GP     40
#define A2_B   (128 * GP * 2)
#define ST2_B  (192 * GP * 2)      // 15360 B / stage
#define NSTGQ  3
#define NITER  (D_ / 32)

// ---------------------------------------------------------------------------
// QKV GEMM (rope/V-transpose epilogue). Per-batch grid (48, 8).
// ---------------------------------------------------------------------------
__global__ __launch_bounds__(128, 3) void gemm_qkv(
    const __half* __restrict__ A,
    const __half* __restrict__ W0, const __half* __restrict__ W1,
    const __half* __restrict__ W2,
    const float* __restrict__ cosb, const float* __restrict__ sinb,
    int mbase)
{
    extern __shared__ __half sh[];
    const int bx = blockIdx.x, by = blockIdx.y;
    const int tid = threadIdx.x, lane = tid & 31, wid = tid >> 5;
    const int g = lane >> 2, t = lane & 3;
    const int wm = wid * 32;

    const __half* Wt;
    int ctile, sel;
    if (bx < 32)      { Wt = W0; ctile = bx;      sel = 0; }
    else if (bx < 40) { Wt = W1; ctile = bx - 32; sel = 1; }
    else              { Wt = W2; ctile = bx - 40; sel = 2; }

    const __half* Ab = A  + (size_t)(mbase + by * 128) * D_;
    const __half* Bb = Wt + (size_t)ctile * 64 * D_;

    const uint32_t sbase = (uint32_t)__cvta_generic_to_shared(sh);

    auto issue = [&](int stage, int k0) {
        uint32_t sa = sbase + stage * ST2_B;
#pragma unroll
        for (int j = 0; j < 4; j++) {
            int idx = tid + j * 128;
            int r = idx >> 2, c = idx & 3;
            cp16(sa + (r * GP + c * 8) * 2, Ab + (size_t)r * D_ + k0 + c * 8);
        }
#pragma unroll
        for (int j = 0; j < 2; j++) {
            int idx = tid + j * 128;
            int r = idx >> 2, c = idx & 3;
            cp16(sa + A2_B + (r * GP + c * 8) * 2, Bb + (size_t)r * D_ + k0 + c * 8);
        }
    };

    uint32_t aoff[2], boff[4];
#pragma unroll
    for (int mt = 0; mt < 2; mt++)
        aoff[mt] = ((wm + mt * 16 + (lane & 7) + ((lane >> 3) & 1) * 8) * GP
                    + (lane >> 4) * 8) * 2;
#pragma unroll
    for (int p = 0; p < 4; p++)
        boff[p] = (uint32_t)A2_B +
                  ((p * 16 + (lane & 7) + ((lane >> 4) & 1) * 8) * GP
                   + ((lane >> 3) & 1) * 8) * 2;

    float acc[2][8][4] = {};

    issue(0, 0);  cp_commit();
    issue(1, 32); cp_commit();

    for (int it = 0; it < NITER; ++it) {
        cp_wait1();
        __syncthreads();          // orders compute(it-1) reads before issue below
        if (it + 2 < NITER) issue((it + 2) % NSTGQ, (it + 2) * 32);
        cp_commit();

        const uint32_t sstg = sbase + (uint32_t)(it % NSTGQ) * ST2_B;
#pragma unroll
        for (int kk = 0; kk < 2; kk++) {
            const uint32_t kb = kk * 32;
            uint32_t af[2][4];
#pragma unroll
            for (int mt = 0; mt < 2; mt++)
                ldsm_x4(af[mt][0], af[mt][1], af[mt][2], af[mt][3],
                        sstg + aoff[mt] + kb);
            uint32_t bf[8][2];
#pragma unroll
            for (int p = 0; p < 4; p++)
                ldsm_x4(bf[2 * p][0], bf[2 * p][1], bf[2 * p + 1][0], bf[2 * p + 1][1],
                        sstg + boff[p] + kb);
#pragma unroll
            for (int mt = 0; mt < 2; mt++)
#pragma unroll
                for (int nt = 0; nt < 8; nt++)
                    mma_f16(acc[mt][nt], af[mt][0], af[mt][1], af[mt][2], af[mt][3],
                            bf[nt][0], bf[nt][1]);
        }
        // no bottom barrier: next iteration's top barrier provides ordering
    }

#pragma unroll
    for (int mt = 0; mt < 2; mt++) {
        const int r0g = mbase + by * 128 + wm + mt * 16 + g;
        const int r1g = r0g + 8;

        if (sel == 2) {
            int b0 = r0g >> 10, s0 = r0g & (S_ - 1);
            int b1 = r1g >> 10, s1 = r1g & (S_ - 1);
#pragma unroll
            for (int nt = 0; nt < 8; nt++) {
                int colk = ctile * 64 + nt * 8 + t * 2;
                int gh = colk >> 6, d = colk & 63;
                size_t base0 = ((size_t)(b0 * HKV_ + gh) * HD_) * S_;
                size_t base1 = ((size_t)(b1 * HKV_ + gh) * HD_) * S_;
                g_vt[base0 + (size_t)d * S_ + s0]       = __float2half(acc[mt][nt][0]);
                g_vt[base0 + (size_t)(d + 1) * S_ + s0] = __float2half(acc[mt][nt][1]);
                g_vt[base1 + (size_t)d * S_ + s1]       = __float2half(acc[mt][nt][2]);
                g_vt[base1 + (size_t)(d + 1) * S_ + s1] = __float2half(acc[mt][nt][3]);
            }
        } else {
            int s0 = r0g & (S_ - 1), s1 = r1g & (S_ - 1);
#pragma unroll
            for (int nt = 0; nt < 4; nt++) {
                int d = nt * 8 + 2 * t;
                float c0a = cosb[s0 * HD_ + d], c0b = cosb[s0 * HD_ + d + 1];
                float z0a = sinb[s0 * HD_ + d], z0b = sinb[s0 * HD_ + d + 1];
                float c1a = cosb[s1 * HD_ + d], c1b = cosb[s1 * HD_ + d + 1];
                float z1a = sinb[s1 * HD_ + d], z1b = sinb[s1 * HD_ + d + 1];
                float a, b;
                a = acc[mt][nt][0]; b = acc[mt][nt + 4][0];
                acc[mt][nt][0] = a * c0a - b * z0a;  acc[mt][nt + 4][0] = b * c0a + a * z0a;
                a = acc[mt][nt][1]; b = acc[mt][nt + 4][1];
                acc[mt][nt][1] = a * c0b - b * z0b;  acc[mt][nt + 4][1] = b * c0b + a * z0b;
                a = acc[mt][nt][2]; b = acc[mt][nt + 4][2];
                acc[mt][nt][2] = a * c1a - b * z1a;  acc[mt][nt + 4][2] = b * c1a + a * z1a;
                a = acc[mt][nt][3]; b = acc[mt][nt + 4][3];
                acc[mt][nt][3] = a * c1b - b * z1b;  acc[mt][nt + 4][3] = b * c1b + a * z1b;
            }
            __half* dst = (sel == 0) ? g_qh : g_kh;
            const int pitch = (sel == 0) ? NQ_ : NKV_;
            const int cb = ctile * 64;
#pragma unroll
            for (int nt = 0; nt < 8; nt++) {
                int col = cb + nt * 8 + t * 2;
                *(__half2*)&dst[(size_t)r0g * pitch + col] =
                    __floats2half2_rn(acc[mt][nt][0], acc[mt][nt][1]);
                *(__half2*)&dst[(size_t)r1g * pitch + col] =
                    __floats2half2_rn(acc[mt][nt][2], acc[mt][nt][3]);
            }
        }
    }
}

// ---------------------------------------------------------------------------
// O-projection GEMM: 128x64 tiles, 3 stages, 3 CTAs/SM. Per-batch (32, 8).
// ---------------------------------------------------------------------------
__global__ __launch_bounds__(128, 3) void gemm_o(
    const __half* __restrict__ A,
    const __half* __restrict__ W0,
    float* __restrict__ Cf, int mbase)
{
    extern __shared__ __half sh[];
    const int bx = blockIdx.x, by = blockIdx.y;
    const int tid = threadIdx.x, lane = tid & 31, wid = tid >> 5;
    const int g = lane >> 2, t = lane & 3;
    const int wm = wid * 32;

    const __half* Ab = A  + (size_t)(mbase + by * 128) * D_;
    const __half* Bb = W0 + (size_t)bx * 64 * D_;

    const uint32_t sbase = (uint32_t)__cvta_generic_to_shared(sh);

    auto issue = [&](int stage, int k0) {
        uint32_t sa = sbase + stage * ST2_B;
#pragma unroll
        for (int j = 0; j < 4; j++) {
            int idx = tid + j * 128;
            int r = idx >> 2, c = idx & 3;
            cp16(sa + (r * GP + c * 8) * 2, Ab + (size_t)r * D_ + k0 + c * 8);
        }
#pragma unroll
        for (int j = 0; j < 2; j++) {
            int idx = tid + j * 128;
            int r = idx >> 2, c = idx & 3;
            cp16(sa + A2_B + (r * GP + c * 8) * 2, Bb + (size_t)r * D_ + k0 + c * 8);
        }
    };

    uint32_t aoff[2], boff[4];
#pragma unroll
    for (int mt = 0; mt < 2; mt++)
        aoff[mt] = ((wm + mt * 16 + (lane & 7) + ((lane >> 3) & 1) * 8) * GP
                    + (lane >> 4) * 8) * 2;
#pragma unroll
    for (int p = 0; p < 4; p++)
        boff[p] = (uint32_t)A2_B +
                  ((p * 16 + (lane & 7) + ((lane >> 4) & 1) * 8) * GP
                   + ((lane >> 3) & 1) * 8) * 2;

    float acc[2][8][4] = {};

    issue(0, 0);  cp_commit();
    issue(1, 32); cp_commit();

    for (int it = 0; it < NITER; ++it) {
        cp_wait1();
        __syncthreads();
        if (it + 2 < NITER) issue((it + 2) % NSTGQ, (it + 2) * 32);
        cp_commit();

        const uint32_t sstg = sbase + (uint32_t)(it % NSTGQ) * ST2_B;
#pragma unroll
        for (int kk = 0; kk < 2; kk++) {
            const uint32_t kb = kk * 32;
            uint32_t af[2][4];
#pragma unroll
            for (int mt = 0; mt < 2; mt++)
                ldsm_x4(af[mt][0], af[mt][1], af[mt][2], af[mt][3],
                        sstg + aoff[mt] + kb);
            uint32_t bf[8][2];
#pragma unroll
            for (int p = 0; p < 4; p++)
                ldsm_x4(bf[2 * p][0], bf[2 * p][1], bf[2 * p + 1][0], bf[2 * p + 1][1],
                        sstg + boff[p] + kb);
#pragma unroll
            for (int mt = 0; mt < 2; mt++)
#pragma unroll
                for (int nt = 0; nt < 8; nt++)
                    mma_f16(acc[mt][nt], af[mt][0], af[mt][1], af[mt][2], af[mt][3],
                            bf[nt][0], bf[nt][1]);
        }
        // no bottom barrier
    }

#pragma unroll
    for (int mt = 0; mt < 2; mt++) {
        const int r0g = mbase + by * 128 + wm + mt * 16 + g;
        const int r1g = r0g + 8;
#pragma unroll
        for (int nt = 0; nt < 8; nt++) {
            int col = bx * 64 + nt * 8 + t * 2;
            *(float2*)&Cf[(size_t)r0g * NQ_ + col] =
                make_float2(acc[mt][nt][0], acc[mt][nt][1]);
            *(float2*)&Cf[(size_t)r1g * NQ_ + col] =
                make_float2(acc[mt][nt][2], acc[mt][nt][3]);
        }
    }
}

// ---------------------------------------------------------------------------
// Flash attention: balanced tile pairing + register-direct P + async Q load.
// grid (4, 32) per batch; CTA x does q-tiles {x, 7-x}.
// ---------------------------------------------------------------------------
#define FP_   72
#define KVT_B (64 * FP_ * 2)
#define FQ_OFF 0
#define FK_OFF 18432
#define FV_OFF 36864
#define FSMEM  55296

__global__ __launch_bounds__(256) void flash_h(
    const __half* __restrict__ Q,
    const __half* __restrict__ K,
    const __half* __restrict__ Vt,
    __half* __restrict__ Ctx, int b)
{
    extern __shared__ __half fsh[];
    const uint32_t sb  = (uint32_t)__cvta_generic_to_shared(fsh);
    const uint32_t qsb = sb + FQ_OFF;
    const uint32_t ksb = sb + FK_OFF;
    const uint32_t vsb = sb + FV_OFF;

    const int h   = blockIdx.y;
    const int gh  = h / REP_;
    const int tid = threadIdx.x;
    const int lane = tid & 31;
    const int wid  = tid >> 5;
    const int g    = lane >> 2;
    const int t    = lane & 3;
    const int r0   = wid * 16 + g;

    const uint32_t aoff = ((wid * 16 + (lane & 7) + ((lane >> 3) & 1) * 8) * FP_
                           + (lane >> 4) * 8) * 2;
    uint32_t boff[4];
#pragma unroll
    for (int p = 0; p < 4; p++)
        boff[p] = ((p * 16 + (lane & 7) + ((lane >> 4) & 1) * 8) * FP_
                   + ((lane >> 3) & 1) * 8) * 2;

    const __half* Kbase  = K  + ((size_t)(b * S_)) * NKV_ + gh * HD_;
    const __half* Vtbase = Vt + ((size_t)(b * HKV_ + gh)) * HD_ * S_;
    auto loadKV = [&](int st, int kt) {
        uint32_t kst = ksb + st * KVT_B;
        uint32_t vst = vsb + st * KVT_B;
        const __half* Kb  = Kbase  + (size_t)(kt * 64) * NKV_;
        const __half* Vtb = Vtbase + kt * 64;
#pragma unroll
        for (int j = 0; j < 2; j++) {
            int idx = tid + j * 256;
            int r = idx >> 3, c = idx & 7;
            cp16(kst + r * 144 + c * 16, Kb  + (size_t)r * NKV_ + c * 8);
            cp16(vst + r * 144 + c * 16, Vtb + (size_t)r * S_ + c * 8);
        }
    };

#pragma unroll 1
    for (int half = 0; half < 2; half++) {
        const int qt = (half == 0) ? (int)blockIdx.x : 7 - (int)blockIdx.x;
        const int ktmax = 2 * qt + 1;

        __syncthreads();   // all warps done with previous tile's smem

        // async Q tile load (128 x 64) folded into group 0 with KV0
        const __half* Qb = Q + ((size_t)(b * S_ + qt * 128)) * NQ_ + h * HD_;
#pragma unroll
        for (int j = 0; j < 4; j++) {
            int idx = tid + j * 256;
            int r = idx >> 3, c = idx & 7;
            cp16(qsb + (r * FP_ + c * 8) * 2, Qb + (size_t)r * NQ_ + c * 8);
        }
        loadKV(0, 0);
        cp_commit();       // G0 = Q + KV0

        float m0 = -INFINITY, m1 = -INFINITY, l0 = 0.f, l1 = 0.f;
        float oc[8][4] = {};

        for (int kt = 0; kt <= ktmax; kt++) {
            __syncthreads();
            int ktn = (kt + 1 <= ktmax) ? kt + 1 : ktmax;
            loadKV((kt + 1) & 1, ktn);
            cp_commit();
            cp_wait1();
            __syncthreads();

            const uint32_t kstg = ksb + (uint32_t)(kt & 1) * KVT_B;
            const uint32_t vstg = vsb + (uint32_t)(kt & 1) * KVT_B;

            // S = Q K^T
            float sc[8][4] = {};
#pragma unroll
            for (int kk = 0; kk < 4; kk++) {
                const uint32_t kb = kk * 32;
                uint32_t a0, a1, a2, a3;
                ldsm_x4(a0, a1, a2, a3, qsb + aoff + kb);
                uint32_t bf[8][2];
#pragma unroll
                for (int p = 0; p < 4; p++)
                    ldsm_x4(bf[2 * p][0], bf[2 * p][1], bf[2 * p + 1][0], bf[2 * p + 1][1],
                            kstg + boff[p] + kb);
#pragma unroll
                for (int nt = 0; nt < 8; nt++)
                    mma_f16(sc[nt], a0, a1, a2, a3, bf[nt][0], bf[nt][1]);
            }

            const bool diag = (kt * 64 + 63 > qt * 128 + wid * 16);
            const int gr0 = qt * 128 + r0;
            const int gc0 = kt * 64 + t * 2;
            float mn0 = m0, mn1 = m1;
#pragma unroll
            for (int nt = 0; nt < 8; nt++) {
#pragma unroll
                for (int j = 0; j < 4; j++) sc[nt][j] *= 0.125f;
                if (diag) {
                    int gc = gc0 + nt * 8;
                    if (gc     > gr0)     sc[nt][0] = -INFINITY;
                    if (gc + 1 > gr0)     sc[nt][1] = -INFINITY;
                    if (gc     > gr0 + 8) sc[nt][2] = -INFINITY;
                    if (gc + 1 > gr0 + 8) sc[nt][3] = -INFINITY;
                }
                mn0 = fmaxf(mn0, fmaxf(sc[nt][0], sc[nt][1]));
                mn1 = fmaxf(mn1, fmaxf(sc[nt][2], sc[nt][3]));
            }
            mn0 = fmaxf(mn0, __shfl_xor_sync(0xffffffffu, mn0, 1));
            mn0 = fmaxf(mn0, __shfl_xor_sync(0xffffffffu, mn0, 2));
            mn1 = fmaxf(mn1, __shfl_xor_sync(0xffffffffu, mn1, 1));
            mn1 = fmaxf(mn1, __shfl_xor_sync(0xffffffffu, mn1, 2));

            float al0 = __expf(m0 - mn0);
            float al1 = __expf(m1 - mn1);
            m0 = mn0; m1 = mn1;

            float rs0 = 0.f, rs1 = 0.f;
            uint32_t p01[8], p23[8];
#pragma unroll
            for (int nt = 0; nt < 8; nt++) {
                sc[nt][0] = __expf(sc[nt][0] - mn0);
                sc[nt][1] = __expf(sc[nt][1] - mn0);
                sc[nt][2] = __expf(sc[nt][2] - mn1);
                sc[nt][3] = __expf(sc[nt][3] - mn1);
                rs0 += sc[nt][0] + sc[nt][1];
                rs1 += sc[nt][2] + sc[nt][3];
                p01[nt] = packh2(sc[nt][0], sc[nt][1]);
                p23[nt] = packh2(sc[nt][2], sc[nt][3]);
            }
            rs0 += __shfl_xor_sync(0xffffffffu, rs0, 1);
            rs0 += __shfl_xor_sync(0xffffffffu, rs0, 2);
            rs1 += __shfl_xor_sync(0xffffffffu, rs1, 1);
            rs1 += __shfl_xor_sync(0xffffffffu, rs1, 2);
            l0 = l0 * al0 + rs0;
            l1 = l1 * al1 + rs1;

#pragma unroll
            for (int dt = 0; dt < 8; dt++) {
                oc[dt][0] *= al0; oc[dt][1] *= al0;
                oc[dt][2] *= al1; oc[dt][3] *= al1;
            }

            // O += P @ V — A-fragments straight from the S C-fragments
#pragma unroll
            for (int p = 0; p < 4; p++) {
                const uint32_t kb = p * 32;
                uint32_t a0 = p01[2 * p];
                uint32_t a1 = p23[2 * p];
                uint32_t a2 = p01[2 * p + 1];
                uint32_t a3 = p23[2 * p + 1];
                uint32_t bf[8][2];
#pragma unroll
                for (int q = 0; q < 4; q++)
                    ldsm_x4(bf[2 * q][0], bf[2 * q][1], bf[2 * q + 1][0], bf[2 * q + 1][1],
                            vstg + boff[q] + kb);
#pragma unroll
                for (int dt = 0; dt < 8; dt++)
                    mma_f16(oc[dt], a0, a1, a2, a3, bf[dt][0], bf[dt][1]);
            }
        }
        cp_wait0();

        const float inv0 = 1.f / l0;
        const float inv1 = 1.f / l1;
        __half* Ob = Ctx + ((size_t)(b * S_ + qt * 128)) * NQ_ + h * HD_;
#pragma unroll
        for (int dt = 0; dt < 8; dt++) {
            int c = dt * 8 + t * 2;
            *(__half2*)&Ob[(size_t)r0 * NQ_ + c] =
                __floats2half2_rn(oc[dt][0] * inv0, oc[dt][1] * inv0);
            *(__half2*)&Ob[(size_t)(r0 + 8) * NQ_ + c] =
                __floats2half2_rn(oc[dt][2] * inv1, oc[dt][3] * inv1);
        }
    }
}

// ---------------------------------------------------------------------------
// Host launch: two batch chains + parallel prologue (persistent streams).
// ---------------------------------------------------------------------------
extern "C" void kernel_launch(void* const* d_in, const int* in_sizes, int n_in,
                              void* d_out, int out_size)
{
    const float* x    = (const float*)d_in[0];
    const float* wq   = (const float*)d_in[1];
    const float* wk   = (const float*)d_in[2];
    const float* wv   = (const float*)d_in[3];
    const float* wo   = (const float*)d_in[4];
    const float* cosb = (const float*)d_in[5];
    const float* sinb = (const float*)d_in[6];
    float* out = (float*)d_out;

    __half *xh, *wqt, *wkt, *wvt, *wot, *qh, *kh, *vt, *ctxh;
    cudaGetSymbolAddress((void**)&xh,   g_xh);
    cudaGetSymbolAddress((void**)&wqt,  g_wqt);
    cudaGetSymbolAddress((void**)&wkt,  g_wkt);
    cudaGetSymbolAddress((void**)&wvt,  g_wvt);
    cudaGetSymbolAddress((void**)&wot,  g_wot);
    cudaGetSymbolAddress((void**)&qh,   g_qh);
    cudaGetSymbolAddress((void**)&kh,   g_kh);
    cudaGetSymbolAddress((void**)&vt,   g_vt);
    cudaGetSymbolAddress((void**)&ctxh, g_ctxh);

    const int smem_g = NSTGQ * ST2_B;   // 46080
    cudaFuncSetAttribute(gemm_qkv, cudaFuncAttributeMaxDynamicSharedMemorySize, smem_g);
    cudaFuncSetAttribute(gemm_o,   cudaFuncAttributeMaxDynamicSharedMemorySize, smem_g);
    cudaFuncSetAttribute(flash_h,  cudaFuncAttributeMaxDynamicSharedMemorySize, FSMEM);

    cudaStream_t s1 = g_sc.s1, s2 = g_sc.s2, s3 = g_sc.s3;
    const int HB4 = S_ * D_ / 4;

    // fork
    cudaEventRecord(g_sc.eFork, 0);
    cudaStreamWaitEvent(s1, g_sc.eFork, 0);
    cudaStreamWaitEvent(s2, g_sc.eFork, 0);
    cudaStreamWaitEvent(s3, g_sc.eFork, 0);

    // prologue (concurrent)
    conv_x<<<(HB4 + 255) / 256, 256, 0, 0>>>(x, xh, HB4);                       // b0
    conv_x<<<(HB4 + 255) / 256, 256, 0, s3>>>(x + S_ * D_, xh + S_ * D_, HB4);  // b1
    cudaEventRecord(g_sc.eConv1, s3);

    transp<<<dim3(NQ_ / 32, D_ / 32, 1), dim3(32, 8), 0, s1>>>(wq, wq, wqt, wqt, NQ_);
    cudaEventRecord(g_sc.eTwq, s1);

    transp<<<dim3(NKV_ / 32, D_ / 32, 2), dim3(32, 8), 0, s2>>>(wk, wv, wkt, wvt, NKV_);
    cudaEventRecord(g_sc.eTwkv, s2);
    transp<<<dim3(NQ_ / 32, D_ / 32, 1), dim3(32, 8), 0, s2>>>(wo, wo, wot, wot, NQ_);
    cudaEventRecord(g_sc.eWo, s2);

    // chain b0 on default stream
    cudaStreamWaitEvent(0, g_sc.eTwq, 0);
    cudaStreamWaitEvent(0, g_sc.eTwkv, 0);
    gemm_qkv<<<dim3(48, 8), 128, smem_g, 0>>>(xh, wqt, wkt, wvt, cosb, sinb, 0);
    flash_h<<<dim3(4, 32), 256, FSMEM, 0>>>(qh, kh, vt, ctxh, 0);
    cudaStreamWaitEvent(0, g_sc.eWo, 0);
    gemm_o<<<dim3(32, 8), 128, smem_g, 0>>>(ctxh, wot, out, 0);

    // chain b1 on s1
    cudaStreamWaitEvent(s1, g_sc.eTwkv, 0);
    cudaStreamWaitEvent(s1, g_sc.eConv1, 0);
    gemm_qkv<<<dim3(48, 8), 128, smem_g, s1>>>(xh, wqt, wkt, wvt, cosb, sinb, S_);
    flash_h<<<dim3(4, 32), 256, FSMEM, s1>>>(qh, kh, vt, ctxh, 1);
    cudaStreamWaitEvent(s1, g_sc.eWo, 0);
    gemm_o<<<dim3(32, 8), 128, smem_g, s1>>>(ctxh, wot, out, S_);
    cudaEventRecord(g_sc.eC1, s1);

    // join
    cudaStreamWaitEvent(0, g_sc.eC1, 0);
}

// round 17
// speedup vs baseline: 1.1280x; 1.0139x over previous
#include <cuda_runtime.h>
#include <cuda_fp16.h>
#include <math.h>
#include <stdint.h>

#define B_    2
#define S_    1024
#define D_    2048
#define H_    32
#define HKV_  8
#define HD_   64
#define REP_  4
#define M_    (B_ * S_)       // 2048
#define NQ_   (H_ * HD_)      // 2048
#define NKV_  (HKV_ * HD_)    // 512

// ---------------------------------------------------------------------------
// Device-global scratch (no cudaMalloc allowed)
// ---------------------------------------------------------------------------
__device__ __half g_xh [M_ * D_];
__device__ __half g_wqt[NQ_ * D_];
__device__ __half g_wkt[NKV_ * D_];
__device__ __half g_wvt[NKV_ * D_];
__device__ __half g_wot[D_ * NQ_];
__device__ __half g_qh [M_ * NQ_];
__device__ __half g_kh [M_ * NKV_];
__device__ __half g_vt [B_ * HKV_ * HD_ * S_];   // [b][gh][d][s]
__device__ __half g_ctxh[M_ * NQ_];

// ---------------------------------------------------------------------------
// Persistent streams/events (created once pre-main; never in kernel_launch)
// ---------------------------------------------------------------------------
struct StreamCtx {
    cudaStream_t s1, s2, s3;
    cudaEvent_t  eFork, eTwq, eTwkv, eWo, eConv1, eC1;
    StreamCtx() {
        cudaStreamCreateWithFlags(&s1, cudaStreamNonBlocking);
        cudaStreamCreateWithFlags(&s2, cudaStreamNonBlocking);
        cudaStreamCreateWithFlags(&s3, cudaStreamNonBlocking);
        cudaEvent_t* evs[] = {&eFork, &eTwq, &eTwkv, &eWo, &eConv1, &eC1};
        for (auto e : evs) cudaEventCreateWithFlags(e, cudaEventDisableTiming);
    }
};
static StreamCtx g_sc;

// ---------------------------------------------------------------------------
// device helpers
// ---------------------------------------------------------------------------
__device__ __forceinline__ void mma_f16(float* c,
        uint32_t a0, uint32_t a1, uint32_t a2, uint32_t a3,
        uint32_t b0, uint32_t b1) {
    asm volatile(
        "mma.sync.aligned.m16n8k16.row.col.f32.f16.f16.f32 "
        "{%0,%1,%2,%3}, {%4,%5,%6,%7}, {%8,%9}, {%0,%1,%2,%3};"
        : "+f"(c[0]), "+f"(c[1]), "+f"(c[2]), "+f"(c[3])
        : "r"(a0), "r"(a1), "r"(a2), "r"(a3), "r"(b0), "r"(b1));
}

__device__ __forceinline__ void ldsm_x4(uint32_t& r0, uint32_t& r1,
                                        uint32_t& r2, uint32_t& r3, uint32_t addr) {
    asm volatile("ldmatrix.sync.aligned.m8n8.x4.shared.b16 {%0,%1,%2,%3}, [%4];"
                 : "=r"(r0), "=r"(r1), "=r"(r2), "=r"(r3) : "r"(addr));
}

__device__ __forceinline__ void cp16(uint32_t saddr, const void* gptr) {
    asm volatile("cp.async.cg.shared.global [%0], [%1], 16;"
                 :: "r"(saddr), "l"(gptr) : "memory");
}
__device__ __forceinline__ void cp_commit() {
    asm volatile("cp.async.commit_group;" ::: "memory");
}
__device__ __forceinline__ void cp_wait1() {
    asm volatile("cp.async.wait_group 1;" ::: "memory");
}
__device__ __forceinline__ void cp_wait0() {
    asm volatile("cp.async.wait_group 0;" ::: "memory");
}

__device__ __forceinline__ uint32_t packh2(float a, float b) {
    __half2 hv = __floats2half2_rn(a, b);
    return *reinterpret_cast<uint32_t*>(&hv);
}

// ---------------------------------------------------------------------------
// Converters
// ---------------------------------------------------------------------------
__global__ void conv_x(const float* __restrict__ x, __half* __restrict__ xh, int n4)
{
    int i = blockIdx.x * 256 + threadIdx.x;
    if (i >= n4) return;
    float4 v = ((const float4*)x)[i];
    ((__half2*)xh)[i * 2]     = __floats2half2_rn(v.x, v.y);
    ((__half2*)xh)[i * 2 + 1] = __floats2half2_rn(v.z, v.w);
}

// Vectorized transpose+convert: src [D][N] fp32 -> dst [N][D] half.
// 64 (n) x 32 (k) tile per block, 256 threads.
// Load: float2 per thread (coalesced along n). Store: half2 per thread
// (coalesced along k), 2 k-values per write.
__global__ void transp(const float* __restrict__ s0, const float* __restrict__ s1,
                       __half* __restrict__ d0, __half* __restrict__ d1, int N)
{
    const float* src = blockIdx.z ? s1 : s0;
    __half*      dst = blockIdx.z ? d1 : d0;
    __shared__ __half t[64][34];          // [n][k], pitch 34 halves
    const int n0 = blockIdx.x * 64, k0 = blockIdx.y * 32;
    const int tid = threadIdx.x;

    // load 32 k-rows x 64 n-cols: each thread one float2 (2 n-values)
    {
        int r = tid >> 5;                 // 0..7 (k within group)
        int c = (tid & 31) * 2;           // 0..62 (n)
#pragma unroll
        for (int j = 0; j < 4; j++) {
            int k = r + j * 8;
            float2 v = *(const float2*)(src + (size_t)(k0 + k) * N + n0 + c);
            t[c][k]     = __float2half(v.x);
            t[c + 1][k] = __float2half(v.y);
        }
    }
    __syncthreads();

    // store 64 n-rows x 32 k-cols: each thread half2 (2 k-values)
    {
        int n = tid >> 4;                 // 0..15
        int kc = (tid & 15) * 2;          // 0..30
#pragma unroll
        for (int j = 0; j < 4; j++) {
            int nn = n + j * 16;
            *(__half2*)&dst[(size_t)(n0 + nn) * D_ + k0 + kc] =
                *(__half2*)&t[nn][kc];
        }
    }
}

// ---------------------------------------------------------------------------
// Shared GEMM config: 128x64 CTA tile, 4 warps (32x64 warp tile), 3 stages.
// ---------------------------------------------------------------------------
#define GP     40
#define A2_B   (128 * GP * 2)
#define ST2_B  (192 * GP * 2)      // 15360 B / stage
#define NSTGQ  3
#define NITER  (D_ / 32)

// ---------------------------------------------------------------------------
// QKV GEMM (rope/V-transpose epilogue). Per-batch grid (48, 8).
// ---------------------------------------------------------------------------
__global__ __launch_bounds__(128, 3) void gemm_qkv(
    const __half* __restrict__ A,
    const __half* __restrict__ W0, const __half* __restrict__ W1,
    const __half* __restrict__ W2,
    const float* __restrict__ cosb, const float* __restrict__ sinb,
    int mbase)
{
    extern __shared__ __half sh[];
    const int bx = blockIdx.x, by = blockIdx.y;
    const int tid = threadIdx.x, lane = tid & 31, wid = tid >> 5;
    const int g = lane >> 2, t = lane & 3;
    const int wm = wid * 32;

    const __half* Wt;
    int ctile, sel;
    if (bx < 32)      { Wt = W0; ctile = bx;      sel = 0; }
    else if (bx < 40) { Wt = W1; ctile = bx - 32; sel = 1; }
    else              { Wt = W2; ctile = bx - 40; sel = 2; }

    const __half* Ab = A  + (size_t)(mbase + by * 128) * D_;
    const __half* Bb = Wt + (size_t)ctile * 64 * D_;

    const uint32_t sbase = (uint32_t)__cvta_generic_to_shared(sh);

    auto issue = [&](int stage, int k0) {
        uint32_t sa = sbase + stage * ST2_B;
#pragma unroll
        for (int j = 0; j < 4; j++) {
            int idx = tid + j * 128;
            int r = idx >> 2, c = idx & 3;
            cp16(sa + (r * GP + c * 8) * 2, Ab + (size_t)r * D_ + k0 + c * 8);
        }
#pragma unroll
        for (int j = 0; j < 2; j++) {
            int idx = tid + j * 128;
            int r = idx >> 2, c = idx & 3;
            cp16(sa + A2_B + (r * GP + c * 8) * 2, Bb + (size_t)r * D_ + k0 + c * 8);
        }
    };

    uint32_t aoff[2], boff[4];
#pragma unroll
    for (int mt = 0; mt < 2; mt++)
        aoff[mt] = ((wm + mt * 16 + (lane & 7) + ((lane >> 3) & 1) * 8) * GP
                    + (lane >> 4) * 8) * 2;
#pragma unroll
    for (int p = 0; p < 4; p++)
        boff[p] = (uint32_t)A2_B +
                  ((p * 16 + (lane & 7) + ((lane >> 4) & 1) * 8) * GP
                   + ((lane >> 3) & 1) * 8) * 2;

    float acc[2][8][4] = {};

    issue(0, 0);  cp_commit();
    issue(1, 32); cp_commit();

    for (int it = 0; it < NITER; ++it) {
        cp_wait1();
        __syncthreads();
        if (it + 2 < NITER) issue((it + 2) % NSTGQ, (it + 2) * 32);
        cp_commit();

        const uint32_t sstg = sbase + (uint32_t)(it % NSTGQ) * ST2_B;
#pragma unroll
        for (int kk = 0; kk < 2; kk++) {
            const uint32_t kb = kk * 32;
            uint32_t af[2][4];
#pragma unroll
            for (int mt = 0; mt < 2; mt++)
                ldsm_x4(af[mt][0], af[mt][1], af[mt][2], af[mt][3],
                        sstg + aoff[mt] + kb);
            uint32_t bf[8][2];
#pragma unroll
            for (int p = 0; p < 4; p++)
                ldsm_x4(bf[2 * p][0], bf[2 * p][1], bf[2 * p + 1][0], bf[2 * p + 1][1],
                        sstg + boff[p] + kb);
#pragma unroll
            for (int mt = 0; mt < 2; mt++)
#pragma unroll
                for (int nt = 0; nt < 8; nt++)
                    mma_f16(acc[mt][nt], af[mt][0], af[mt][1], af[mt][2], af[mt][3],
                            bf[nt][0], bf[nt][1]);
        }
    }

#pragma unroll
    for (int mt = 0; mt < 2; mt++) {
        const int r0g = mbase + by * 128 + wm + mt * 16 + g;
        const int r1g = r0g + 8;

        if (sel == 2) {
            int b0 = r0g >> 10, s0 = r0g & (S_ - 1);
            int b1 = r1g >> 10, s1 = r1g & (S_ - 1);
#pragma unroll
            for (int nt = 0; nt < 8; nt++) {
                int colk = ctile * 64 + nt * 8 + t * 2;
                int gh = colk >> 6, d = colk & 63;
                size_t base0 = ((size_t)(b0 * HKV_ + gh) * HD_) * S_;
                size_t base1 = ((size_t)(b1 * HKV_ + gh) * HD_) * S_;
                g_vt[base0 + (size_t)d * S_ + s0]       = __float2half(acc[mt][nt][0]);
                g_vt[base0 + (size_t)(d + 1) * S_ + s0] = __float2half(acc[mt][nt][1]);
                g_vt[base1 + (size_t)d * S_ + s1]       = __float2half(acc[mt][nt][2]);
                g_vt[base1 + (size_t)(d + 1) * S_ + s1] = __float2half(acc[mt][nt][3]);
            }
        } else {
            int s0 = r0g & (S_ - 1), s1 = r1g & (S_ - 1);
#pragma unroll
            for (int nt = 0; nt < 4; nt++) {
                int d = nt * 8 + 2 * t;
                float c0a = cosb[s0 * HD_ + d], c0b = cosb[s0 * HD_ + d + 1];
                float z0a = sinb[s0 * HD_ + d], z0b = sinb[s0 * HD_ + d + 1];
                float c1a = cosb[s1 * HD_ + d], c1b = cosb[s1 * HD_ + d + 1];
                float z1a = sinb[s1 * HD_ + d], z1b = sinb[s1 * HD_ + d + 1];
                float a, b;
                a = acc[mt][nt][0]; b = acc[mt][nt + 4][0];
                acc[mt][nt][0] = a * c0a - b * z0a;  acc[mt][nt + 4][0] = b * c0a + a * z0a;
                a = acc[mt][nt][1]; b = acc[mt][nt + 4][1];
                acc[mt][nt][1] = a * c0b - b * z0b;  acc[mt][nt + 4][1] = b * c0b + a * z0b;
                a = acc[mt][nt][2]; b = acc[mt][nt + 4][2];
                acc[mt][nt][2] = a * c1a - b * z1a;  acc[mt][nt + 4][2] = b * c1a + a * z1a;
                a = acc[mt][nt][3]; b = acc[mt][nt + 4][3];
                acc[mt][nt][3] = a * c1b - b * z1b;  acc[mt][nt + 4][3] = b * c1b + a * z1b;
            }
            __half* dst = (sel == 0) ? g_qh : g_kh;
            const int pitch = (sel == 0) ? NQ_ : NKV_;
            const int cb = ctile * 64;
#pragma unroll
            for (int nt = 0; nt < 8; nt++) {
                int col = cb + nt * 8 + t * 2;
                *(__half2*)&dst[(size_t)r0g * pitch + col] =
                    __floats2half2_rn(acc[mt][nt][0], acc[mt][nt][1]);
                *(__half2*)&dst[(size_t)r1g * pitch + col] =
                    __floats2half2_rn(acc[mt][nt][2], acc[mt][nt][3]);
            }
        }
    }
}

// ---------------------------------------------------------------------------
// O-projection GEMM: 128x64 tiles, 3 stages, 3 CTAs/SM. Per-batch (32, 8).
// ---------------------------------------------------------------------------
__global__ __launch_bounds__(128, 3) void gemm_o(
    const __half* __restrict__ A,
    const __half* __restrict__ W0,
    float* __restrict__ Cf, int mbase)
{
    extern __shared__ __half sh[];
    const int bx = blockIdx.x, by = blockIdx.y;
    const int tid = threadIdx.x, lane = tid & 31, wid = tid >> 5;
    const int g = lane >> 2, t = lane & 3;
    const int wm = wid * 32;

    const __half* Ab = A  + (size_t)(mbase + by * 128) * D_;
    const __half* Bb = W0 + (size_t)bx * 64 * D_;

    const uint32_t sbase = (uint32_t)__cvta_generic_to_shared(sh);

    auto issue = [&](int stage, int k0) {
        uint32_t sa = sbase + stage * ST2_B;
#pragma unroll
        for (int j = 0; j < 4; j++) {
            int idx = tid + j * 128;
            int r = idx >> 2, c = idx & 3;
            cp16(sa + (r * GP + c * 8) * 2, Ab + (size_t)r * D_ + k0 + c * 8);
        }
#pragma unroll
        for (int j = 0; j < 2; j++) {
            int idx = tid + j * 128;
            int r = idx >> 2, c = idx & 3;
            cp16(sa + A2_B + (r * GP + c * 8) * 2, Bb + (size_t)r * D_ + k0 + c * 8);
        }
    };

    uint32_t aoff[2], boff[4];
#pragma unroll
    for (int mt = 0; mt < 2; mt++)
        aoff[mt] = ((wm + mt * 16 + (lane & 7) + ((lane >> 3) & 1) * 8) * GP
                    + (lane >> 4) * 8) * 2;
#pragma unroll
    for (int p = 0; p < 4; p++)
        boff[p] = (uint32_t)A2_B +
                  ((p * 16 + (lane & 7) + ((lane >> 4) & 1) * 8) * GP
                   + ((lane >> 3) & 1) * 8) * 2;

    float acc[2][8][4] = {};

    issue(0, 0);  cp_commit();
    issue(1, 32); cp_commit();

    for (int it = 0; it < NITER; ++it) {
        cp_wait1();
        __syncthreads();
        if (it + 2 < NITER) issue((it + 2) % NSTGQ, (it + 2) * 32);
        cp_commit();

        const uint32_t sstg = sbase + (uint32_t)(it % NSTGQ) * ST2_B;
#pragma unroll
        for (int kk = 0; kk < 2; kk++) {
            const uint32_t kb = kk * 32;
            uint32_t af[2][4];
#pragma unroll
            for (int mt = 0; mt < 2; mt++)
                ldsm_x4(af[mt][0], af[mt][1], af[mt][2], af[mt][3],
                        sstg + aoff[mt] + kb);
            uint32_t bf[8][2];
#pragma unroll
            for (int p = 0; p < 4; p++)
                ldsm_x4(bf[2 * p][0], bf[2 * p][1], bf[2 * p + 1][0], bf[2 * p + 1][1],
                        sstg + boff[p] + kb);
#pragma unroll
            for (int mt = 0; mt < 2; mt++)
#pragma unroll
                for (int nt = 0; nt < 8; nt++)
                    mma_f16(acc[mt][nt], af[mt][0], af[mt][1], af[mt][2], af[mt][3],
                            bf[nt][0], bf[nt][1]);
        }
    }

#pragma unroll
    for (int mt = 0; mt < 2; mt++) {
        const int r0g = mbase + by * 128 + wm + mt * 16 + g;
        const int r1g = r0g + 8;
#pragma unroll
        for (int nt = 0; nt < 8; nt++) {
            int col = bx * 64 + nt * 8 + t * 2;
            *(float2*)&Cf[(size_t)r0g * NQ_ + col] =
                make_float2(acc[mt][nt][0], acc[mt][nt][1]);
            *(float2*)&Cf[(size_t)r1g * NQ_ + col] =
                make_float2(acc[mt][nt][2], acc[mt][nt][3]);
        }
    }
}

// ---------------------------------------------------------------------------
// Flash attention: balanced tile pairing + register-direct P + async Q load.
// grid (4, 32) per batch; CTA x does q-tiles {x, 7-x}. Force 2 CTAs/SM.
// ---------------------------------------------------------------------------
#define FP_   72
#define KVT_B (64 * FP_ * 2)
#define FQ_OFF 0
#define FK_OFF 18432
#define FV_OFF 36864
#define FSMEM  55296

__global__ __launch_bounds__(256, 2) void flash_h(
    const __half* __restrict__ Q,
    const __half* __restrict__ K,
    const __half* __restrict__ Vt,
    __half* __restrict__ Ctx, int b)
{
    extern __shared__ __half fsh[];
    const uint32_t sb  = (uint32_t)__cvta_generic_to_shared(fsh);
    const uint32_t qsb = sb + FQ_OFF;
    const uint32_t ksb = sb + FK_OFF;
    const uint32_t vsb = sb + FV_OFF;

    const int h   = blockIdx.y;
    const int gh  = h / REP_;
    const int tid = threadIdx.x;
    const int lane = tid & 31;
    const int wid  = tid >> 5;
    const int g    = lane >> 2;
    const int t    = lane & 3;
    const int r0   = wid * 16 + g;

    const uint32_t aoff = ((wid * 16 + (lane & 7) + ((lane >> 3) & 1) * 8) * FP_
                           + (lane >> 4) * 8) * 2;
    uint32_t boff[4];
#pragma unroll
    for (int p = 0; p < 4; p++)
        boff[p] = ((p * 16 + (lane & 7) + ((lane >> 4) & 1) * 8) * FP_
                   + ((lane >> 3) & 1) * 8) * 2;

    const __half* Kbase  = K  + ((size_t)(b * S_)) * NKV_ + gh * HD_;
    const __half* Vtbase = Vt + ((size_t)(b * HKV_ + gh)) * HD_ * S_;
    auto loadKV = [&](int st, int kt) {
        uint32_t kst = ksb + st * KVT_B;
        uint32_t vst = vsb + st * KVT_B;
        const __half* Kb  = Kbase  + (size_t)(kt * 64) * NKV_;
        const __half* Vtb = Vtbase + kt * 64;
#pragma unroll
        for (int j = 0; j < 2; j++) {
            int idx = tid + j * 256;
            int r = idx >> 3, c = idx & 7;
            cp16(kst + r * 144 + c * 16, Kb  + (size_t)r * NKV_ + c * 8);
            cp16(vst + r * 144 + c * 16, Vtb + (size_t)r * S_ + c * 8);
        }
    };

#pragma unroll 1
    for (int half = 0; half < 2; half++) {
        const int qt = (half == 0) ? (int)blockIdx.x : 7 - (int)blockIdx.x;
        const int ktmax = 2 * qt + 1;

        __syncthreads();

        // async Q tile load folded into group 0 with KV0
        const __half* Qb = Q + ((size_t)(b * S_ + qt * 128)) * NQ_ + h * HD_;
#pragma unroll
        for (int j = 0; j < 4; j++) {
            int idx = tid + j * 256;
            int r = idx >> 3, c = idx & 7;
            cp16(qsb + (r * FP_ + c * 8) * 2, Qb + (size_t)r * NQ_ + c * 8);
        }
        loadKV(0, 0);
        cp_commit();

        float m0 = -INFINITY, m1 = -INFINITY, l0 = 0.f, l1 = 0.f;
        float oc[8][4] = {};

        for (int kt = 0; kt <= ktmax; kt++) {
            __syncthreads();
            int ktn = (kt + 1 <= ktmax) ? kt + 1 : ktmax;
            loadKV((kt + 1) & 1, ktn);
            cp_commit();
            cp_wait1();
            __syncthreads();

            const uint32_t kstg = ksb + (uint32_t)(kt & 1) * KVT_B;
            const uint32_t vstg = vsb + (uint32_t)(kt & 1) * KVT_B;

            float sc[8][4] = {};
#pragma unroll
            for (int kk = 0; kk < 4; kk++) {
                const uint32_t kb = kk * 32;
                uint32_t a0, a1, a2, a3;
                ldsm_x4(a0, a1, a2, a3, qsb + aoff + kb);
                uint32_t bf[8][2];
#pragma unroll
                for (int p = 0; p < 4; p++)
                    ldsm_x4(bf[2 * p][0], bf[2 * p][1], bf[2 * p + 1][0], bf[2 * p + 1][1],
                            kstg + boff[p] + kb);
#pragma unroll
                for (int nt = 0; nt < 8; nt++)
                    mma_f16(sc[nt], a0, a1, a2, a3, bf[nt][0], bf[nt][1]);
            }

            const bool diag = (kt * 64 + 63 > qt * 128 + wid * 16);
            const int gr0 = qt * 128 + r0;
            const int gc0 = kt * 64 + t * 2;
            float mn0 = m0, mn1 = m1;
#pragma unroll
            for (int nt = 0; nt < 8; nt++) {
#pragma unroll
                for (int j = 0; j < 4; j++) sc[nt][j] *= 0.125f;
                if (diag) {
                    int gc = gc0 + nt * 8;
                    if (gc     > gr0)     sc[nt][0] = -INFINITY;
                    if (gc + 1 > gr0)     sc[nt][1] = -INFINITY;
                    if (gc     > gr0 + 8) sc[nt][2] = -INFINITY;
                    if (gc + 1 > gr0 + 8) sc[nt][3] = -INFINITY;
                }
                mn0 = fmaxf(mn0, fmaxf(sc[nt][0], sc[nt][1]));
                mn1 = fmaxf(mn1, fmaxf(sc[nt][2], sc[nt][3]));
            }
            mn0 = fmaxf(mn0, __shfl_xor_sync(0xffffffffu, mn0, 1));
            mn0 = fmaxf(mn0, __shfl_xor_sync(0xffffffffu, mn0, 2));
            mn1 = fmaxf(mn1, __shfl_xor_sync(0xffffffffu, mn1, 1));
            mn1 = fmaxf(mn1, __shfl_xor_sync(0xffffffffu, mn1, 2));

            float al0 = __expf(m0 - mn0);
            float al1 = __expf(m1 - mn1);
            m0 = mn0; m1 = mn1;

            float rs0 = 0.f, rs1 = 0.f;
            uint32_t p01[8], p23[8];
#pragma unroll
            for (int nt = 0; nt < 8; nt++) {
                sc[nt][0] = __expf(sc[nt][0] - mn0);
                sc[nt][1] = __expf(sc[nt][1] - mn0);
                sc[nt][2] = __expf(sc[nt][2] - mn1);
                sc[nt][3] = __expf(sc[nt][3] - mn1);
                rs0 += sc[nt][0] + sc[nt][1];
                rs1 += sc[nt][2] + sc[nt][3];
                p01[nt] = packh2(sc[nt][0], sc[nt][1]);
                p23[nt] = packh2(sc[nt][2], sc[nt][3]);
            }
            rs0 += __shfl_xor_sync(0xffffffffu, rs0, 1);
            rs0 += __shfl_xor_sync(0xffffffffu, rs0, 2);
            rs1 += __shfl_xor_sync(0xffffffffu, rs1, 1);
            rs1 += __shfl_xor_sync(0xffffffffu, rs1, 2);
            l0 = l0 * al0 + rs0;
            l1 = l1 * al1 + rs1;

#pragma unroll
            for (int dt = 0; dt < 8; dt++) {
                oc[dt][0] *= al0; oc[dt][1] *= al0;
                oc[dt][2] *= al1; oc[dt][3] *= al1;
            }

#pragma unroll
            for (int p = 0; p < 4; p++) {
                const uint32_t kb = p * 32;
                uint32_t a0 = p01[2 * p];
                uint32_t a1 = p23[2 * p];
                uint32_t a2 = p01[2 * p + 1];
                uint32_t a3 = p23[2 * p + 1];
                uint32_t bf[8][2];
#pragma unroll
                for (int q = 0; q < 4; q++)
                    ldsm_x4(bf[2 * q][0], bf[2 * q][1], bf[2 * q + 1][0], bf[2 * q + 1][1],
                            vstg + boff[q] + kb);
#pragma unroll
                for (int dt = 0; dt < 8; dt++)
                    mma_f16(oc[dt], a0, a1, a2, a3, bf[dt][0], bf[dt][1]);
            }
        }
        cp_wait0();

        const float inv0 = 1.f / l0;
        const float inv1 = 1.f / l1;
        __half* Ob = Ctx + ((size_t)(b * S_ + qt * 128)) * NQ_ + h * HD_;
#pragma unroll
        for (int dt = 0; dt < 8; dt++) {
            int c = dt * 8 + t * 2;
            *(__half2*)&Ob[(size_t)r0 * NQ_ + c] =
                __floats2half2_rn(oc[dt][0] * inv0, oc[dt][1] * inv0);
            *(__half2*)&Ob[(size_t)(r0 + 8) * NQ_ + c] =
                __floats2half2_rn(oc[dt][2] * inv1, oc[dt][3] * inv1);
        }
    }
}

// ---------------------------------------------------------------------------
// Host launch: two batch chains + parallel prologue (persistent streams).
// ---------------------------------------------------------------------------
extern "C" void kernel_launch(void* const* d_in, const int* in_sizes, int n_in,
                              void* d_out, int out_size)
{
    const float* x    = (const float*)d_in[0];
    const float* wq   = (const float*)d_in[1];
    const float* wk   = (const float*)d_in[2];
    const float* wv   = (const float*)d_in[3];
    const float* wo   = (const float*)d_in[4];
    const float* cosb = (const float*)d_in[5];
    const float* sinb = (const float*)d_in[6];
    float* out = (float*)d_out;

    __half *xh, *wqt, *wkt, *wvt, *wot, *qh, *kh, *vt, *ctxh;
    cudaGetSymbolAddress((void**)&xh,   g_xh);
    cudaGetSymbolAddress((void**)&wqt,  g_wqt);
    cudaGetSymbolAddress((void**)&wkt,  g_wkt);
    cudaGetSymbolAddress((void**)&wvt,  g_wvt);
    cudaGetSymbolAddress((void**)&wot,  g_wot);
    cudaGetSymbolAddress((void**)&qh,   g_qh);
    cudaGetSymbolAddress((void**)&kh,   g_kh);
    cudaGetSymbolAddress((void**)&vt,   g_vt);
    cudaGetSymbolAddress((void**)&ctxh, g_ctxh);

    const int smem_g = NSTGQ * ST2_B;   // 46080
    cudaFuncSetAttribute(gemm_qkv, cudaFuncAttributeMaxDynamicSharedMemorySize, smem_g);
    cudaFuncSetAttribute(gemm_o,   cudaFuncAttributeMaxDynamicSharedMemorySize, smem_g);
    cudaFuncSetAttribute(flash_h,  cudaFuncAttributeMaxDynamicSharedMemorySize, FSMEM);

    cudaStream_t s1 = g_sc.s1, s2 = g_sc.s2, s3 = g_sc.s3;
    const int HB4 = S_ * D_ / 4;

    // fork
    cudaEventRecord(g_sc.eFork, 0);
    cudaStreamWaitEvent(s1, g_sc.eFork, 0);
    cudaStreamWaitEvent(s2, g_sc.eFork, 0);
    cudaStreamWaitEvent(s3, g_sc.eFork, 0);

    // prologue (concurrent)
    conv_x<<<(HB4 + 255) / 256, 256, 0, 0>>>(x, xh, HB4);                       // b0
    conv_x<<<(HB4 + 255) / 256, 256, 0, s3>>>(x + S_ * D_, xh + S_ * D_, HB4);  // b1
    cudaEventRecord(g_sc.eConv1, s3);

    transp<<<dim3(NQ_ / 64, D_ / 32, 1), dim3(256), 0, s1>>>(wq, wq, wqt, wqt, NQ_);
    cudaEventRecord(g_sc.eTwq, s1);

    transp<<<dim3(NKV_ / 64, D_ / 32, 2), dim3(256), 0, s2>>>(wk, wv, wkt, wvt, NKV_);
    cudaEventRecord(g_sc.eTwkv, s2);
    transp<<<dim3(NQ_ / 64, D_ / 32, 1), dim3(256), 0, s2>>>(wo, wo, wot, wot, NQ_);
    cudaEventRecord(g_sc.eWo, s2);

    // chain b0 on default stream
    cudaStreamWaitEvent(0, g_sc.eTwq, 0);
    cudaStreamWaitEvent(0, g_sc.eTwkv, 0);
    gemm_qkv<<<dim3(48, 8), 128, smem_g, 0>>>(xh, wqt, wkt, wvt, cosb, sinb, 0);
    flash_h<<<dim3(4, 32), 256, FSMEM, 0>>>(qh, kh, vt, ctxh, 0);
    cudaStreamWaitEvent(0, g_sc.eWo, 0);
    gemm_o<<<dim3(32, 8), 128, smem_g, 0>>>(ctxh, wot, out, 0);

    // chain b1 on s1
    cudaStreamWaitEvent(s1, g_sc.eTwkv, 0);
    cudaStreamWaitEvent(s1, g_sc.eConv1, 0);
    gemm_qkv<<<dim3(48, 8), 128, smem_g, s1>>>(xh, wqt, wkt, wvt, cosb, sinb, S_);
    flash_h<<<dim3(4, 32), 256, FSMEM, s1>>>(qh, kh, vt, ctxh, 1);
    cudaStreamWaitEvent(s1, g_sc.eWo, 0);
    gemm_o<<<dim3(32, 8), 128, smem_g, s1>>>(ctxh, wot, out, S_);
    cudaEventRecord(g_sc.eC1, s1);

    // join
    cudaStreamWaitEvent(0, g_sc.eC1, 0);
}